// round 8
// baseline (speedup 1.0000x reference)
#include <cuda_runtime.h>
#include <cuda_bf16.h>
#include <cuda_fp16.h>
#include <cstdint>

// ============================================================================
// RGCN 2-layer, transform-first. Root GEMM fused as a 9th relation.
// GEMMs: mma.sync bf16 2-way split (hi*hi + hi*lo + lo*hi), 3-stage cp.async.
// Messages+root stored fp16. CSR pull aggregation (no atomics), bias in gather.
// ============================================================================

#define MAXN 50000
#define MAXE 840000
#define RELS 8

// Y1ext: [N, 9*256]   (8 relations + root), fp16
// Y2ext: [N, 9*128]
__device__ __half g_Y1[(size_t)MAXN * 2304];
__device__ __half g_Y2[(size_t)MAXN * 1152];
__device__ int    g_cnt[MAXN * RELS];
__device__ int    g_deg[MAXN];
__device__ int    g_offs[MAXN + 1];
__device__ int    g_cur[MAXN];
__device__ unsigned g_csr[MAXE];

__device__ __nv_bfloat16 g_xh[(size_t)MAXN * 256];
__device__ __nv_bfloat16 g_xl[(size_t)MAXN * 256];
__device__ __nv_bfloat16 g_hh[(size_t)MAXN * 256];
__device__ __nv_bfloat16 g_hl[(size_t)MAXN * 256];

// concat weights, pre-transposed+split: [t][k], t = r*ncpr + n, root at RELS*ncpr
__device__ __nv_bfloat16 g_w1h[2304 * 256], g_w1l[2304 * 256];
__device__ __nv_bfloat16 g_w2h[1152 * 256], g_w2l[1152 * 256];

// ---------------------------------------------------------------------------
__device__ __forceinline__ void ldsm4(uint32_t* r, uint32_t addr)
{
    asm volatile("ldmatrix.sync.aligned.m8n8.x4.shared.b16 {%0,%1,%2,%3}, [%4];"
                 : "=r"(r[0]), "=r"(r[1]), "=r"(r[2]), "=r"(r[3]) : "r"(addr));
}

__device__ __forceinline__ void mma_bf16(float* c, const uint32_t* a, const uint32_t* b)
{
    asm volatile(
        "mma.sync.aligned.m16n8k16.row.col.f32.bf16.bf16.f32 "
        "{%0,%1,%2,%3}, {%4,%5,%6,%7}, {%8,%9}, {%0,%1,%2,%3};"
        : "+f"(c[0]), "+f"(c[1]), "+f"(c[2]), "+f"(c[3])
        : "r"(a[0]), "r"(a[1]), "r"(a[2]), "r"(a[3]), "r"(b[0]), "r"(b[1]));
}

#define CP_COMMIT() asm volatile("cp.async.commit_group;" ::: "memory")
#define CP_WAIT1()  asm volatile("cp.async.wait_group 1;" ::: "memory")
#define CP_WAIT0()  asm volatile("cp.async.wait_group 0;" ::: "memory")

__device__ __forceinline__ void cp16(uint32_t dst, const void* src, int sz)
{
    asm volatile("cp.async.ca.shared.global [%0], [%1], 16, %2;"
                 :: "r"(dst), "l"(src), "r"(sz));
}

// ---------------------------------------------------------------------------
// Pipelined GEMM: C[M,T] = A[M,256] @ Bt[T,256]^T, fp16 out.
// CTA 128x128, 8 warps (2x4 of 64x32), kc=32, 3-stage cp.async, 1 sync/iter.
// ---------------------------------------------------------------------------
#define OP_BYTES 10240
#define STG_BYTES 40960
#define SMEMP (3 * STG_BYTES)

__global__ void __launch_bounds__(256)
gemm_pipe(const __nv_bfloat16* __restrict__ Ah, const __nv_bfloat16* __restrict__ Al,
          int M,
          const __nv_bfloat16* __restrict__ Bh, const __nv_bfloat16* __restrict__ Bl,
          __half* __restrict__ C, int ldc)
{
    extern __shared__ char smem[];
    uint32_t sb0;
    asm("{ .reg .u64 t; cvta.to.shared.u64 t, %1; cvt.u32.u64 %0, t; }"
        : "=r"(sb0) : "l"(smem));

    const int tid  = threadIdx.x;
    const int wid  = tid >> 5;
    const int lane = tid & 31;
    const int wm   = wid >> 2;
    const int wn   = wid & 3;
    const int bm   = blockIdx.x * 128;
    const int bn   = blockIdx.y * 128;

    float acc[4][4][4];
#pragma unroll
    for (int i = 0; i < 4; i++)
#pragma unroll
        for (int j = 0; j < 4; j++)
#pragma unroll
            for (int q = 0; q < 4; q++) acc[i][j][q] = 0.f;

    const int q8 = lane >> 3;
    const int lg = lane & 7;

    auto load_stage = [&](int stage, int k0) {
        uint32_t sb = sb0 + stage * STG_BYTES;
#pragma unroll
        for (int i = 0; i < 8; i++) {
            int c   = tid + i * 256;
            int op  = i >> 1;
            int idx = c & 511;
            int row = idx >> 2;
            int seg = (idx & 3) * 8;
            const __nv_bfloat16* g;
            int grow;
            int sz = 16;
            if (op == 0)      { g = Ah; grow = bm + row; if (grow >= M) { grow = 0; sz = 0; } }
            else if (op == 1) { g = Al; grow = bm + row; if (grow >= M) { grow = 0; sz = 0; } }
            else if (op == 2) { g = Bh; grow = bn + row; }
            else              { g = Bl; grow = bn + row; }
            cp16(sb + op * OP_BYTES + row * 80 + seg * 2,
                 g + (size_t)grow * 256 + k0 + seg, sz);
        }
        CP_COMMIT();
    };

    load_stage(0, 0);
    load_stage(1, 32);

    for (int kb = 0; kb < 8; kb++) {
        if (kb < 7) CP_WAIT1(); else CP_WAIT0();
        __syncthreads();
        if (kb + 2 < 8) load_stage((kb + 2) % 3, (kb + 2) * 32);

        const uint32_t sb = sb0 + (kb % 3) * STG_BYTES;
        const uint32_t sAh_b = sb;
        const uint32_t sAl_b = sb + OP_BYTES;
        const uint32_t sBh_b = sb + 2 * OP_BYTES;
        const uint32_t sBl_b = sb + 3 * OP_BYTES;

#pragma unroll
        for (int ks = 0; ks < 2; ks++) {
            uint32_t bh[8], bl[8];
#pragma unroll
            for (int np = 0; np < 2; np++) {
                int nrow = wn * 32 + np * 16 + lg + ((q8 >> 1) ? 8 : 0);
                int bcol = ks * 32 + ((q8 & 1) ? 16 : 0);
                ldsm4(&bh[np * 4], sBh_b + nrow * 80 + bcol);
                ldsm4(&bl[np * 4], sBl_b + nrow * 80 + bcol);
            }
#pragma unroll
            for (int mt = 0; mt < 4; mt++) {
                int arow = wm * 64 + mt * 16 + lg + ((q8 & 1) ? 8 : 0);
                int acol = ks * 32 + ((q8 >> 1) ? 16 : 0);
                uint32_t ah[4], al[4];
                ldsm4(ah, sAh_b + arow * 80 + acol);
                ldsm4(al, sAl_b + arow * 80 + acol);
#pragma unroll
                for (int nt = 0; nt < 4; nt++) mma_bf16(acc[mt][nt], ah, &bh[nt * 2]);
#pragma unroll
                for (int nt = 0; nt < 4; nt++) mma_bf16(acc[mt][nt], ah, &bl[nt * 2]);
#pragma unroll
                for (int nt = 0; nt < 4; nt++) mma_bf16(acc[mt][nt], al, &bh[nt * 2]);
            }
        }
    }

    // ---- epilogue (fp16) ----
#pragma unroll
    for (int mt = 0; mt < 4; mt++) {
#pragma unroll
        for (int nt = 0; nt < 4; nt++) {
            int gr0  = bm + wm * 64 + mt * 16 + (lane >> 2);
            int gcol = bn + wn * 32 + nt * 8 + (lane & 3) * 2;
#pragma unroll
            for (int h = 0; h < 2; h++) {
                int gr = gr0 + h * 8;
                if (gr < M) {
                    *(__half2*)(C + (size_t)gr * ldc + gcol) =
                        __floats2half2_rn(acc[mt][nt][h * 2 + 0], acc[mt][nt][h * 2 + 1]);
                }
            }
        }
    }
}

// ---------------------------------------------------------------------------
// Prep kernels
// ---------------------------------------------------------------------------
__global__ void convw_kernel(const float* __restrict__ W,
                             __nv_bfloat16* __restrict__ hi,
                             __nv_bfloat16* __restrict__ lo,
                             int N, int total)
{
    int idx = blockIdx.x * blockDim.x + threadIdx.x;
    if (idx >= total) return;
    int n = idx % N;
    int k = (idx / N) & 255;
    int r = idx / (N * 256);
    float f = W[idx];
    __nv_bfloat16 h = __float2bfloat16(f);
    __nv_bfloat16 l = __float2bfloat16(f - __bfloat162float(h));
    size_t o = ((size_t)r * N + n) * 256 + k;
    hi[o] = h;
    lo[o] = l;
}

__global__ void split_kernel(const float* __restrict__ X,
                             __nv_bfloat16* __restrict__ hi,
                             __nv_bfloat16* __restrict__ lo,
                             size_t total)
{
    size_t i = (size_t)blockIdx.x * blockDim.x + threadIdx.x;
    if (i >= total) return;
    float f = X[i];
    __nv_bfloat16 h = __float2bfloat16(f);
    hi[i] = h;
    lo[i] = __float2bfloat16(f - __bfloat162float(h));
}

// ---------------------------------------------------------------------------
// CSR construction
// ---------------------------------------------------------------------------
__global__ void zero_int_kernel(int* p, int n)
{
    int i = blockIdx.x * blockDim.x + threadIdx.x;
    if (i < n) p[i] = 0;
}

__global__ void count_kernel(const int* __restrict__ ei,
                             const int* __restrict__ et,
                             int* __restrict__ cnt, int E)
{
    int e = blockIdx.x * blockDim.x + threadIdx.x;
    if (e < E) atomicAdd(&cnt[ei[E + e] * RELS + et[e]], 1);
}

__global__ void deg_kernel(const int* __restrict__ cnt, int* __restrict__ deg, int n)
{
    int i = blockIdx.x * blockDim.x + threadIdx.x;
    if (i < n) {
        int s = 0;
#pragma unroll
        for (int r = 0; r < RELS; r++) s += cnt[i * RELS + r];
        deg[i] = s;
    }
}

__global__ void scan_kernel(const int* __restrict__ deg, int* __restrict__ offs, int n)
{
    __shared__ int buf[1024];
    __shared__ int carry;
    const int tid = threadIdx.x;
    if (tid == 0) carry = 0;
    __syncthreads();
    for (int base = 0; base < n; base += 1024) {
        int i = base + tid;
        int v = (i < n) ? deg[i] : 0;
        buf[tid] = v;
        __syncthreads();
        for (int d = 1; d < 1024; d <<= 1) {
            int t = (tid >= d) ? buf[tid - d] : 0;
            __syncthreads();
            buf[tid] += t;
            __syncthreads();
        }
        if (i < n) offs[i] = carry + buf[tid] - v;
        __syncthreads();
        if (tid == 0) carry += buf[1023];
        __syncthreads();
    }
    if (tid == 0) offs[n] = carry;
}

__global__ void fill_kernel(const int* __restrict__ ei,
                            const int* __restrict__ et,
                            const int* __restrict__ offs,
                            int* __restrict__ cur,
                            unsigned* __restrict__ csr, int E)
{
    int e = blockIdx.x * blockDim.x + threadIdx.x;
    if (e < E) {
        int d = ei[E + e];
        int pos = offs[d] + atomicAdd(&cur[d], 1);
        csr[pos] = (unsigned)ei[e] | ((unsigned)et[e] << 16);
    }
}

// ---------------------------------------------------------------------------
// Gather. Layer 1: root(from Y1ext)+bias+messages, relu, bf16 split. 128 thr.
// ---------------------------------------------------------------------------
__global__ void __launch_bounds__(128)
gather1_kernel(const __half* __restrict__ Y,
               const unsigned* __restrict__ csr,
               const int* __restrict__ offs,
               const int* __restrict__ cnt,
               const float* __restrict__ bias,
               __nv_bfloat16* __restrict__ hh,
               __nv_bfloat16* __restrict__ hl)
{
    const int dst = blockIdx.x;
    const int tid = threadIdx.x;
    __shared__ float nrm[8];
    if (tid < 8) nrm[tid] = 1.0f / (float)max(cnt[dst * RELS + tid], 1);
    const int s = offs[dst], t = offs[dst + 1];
    __syncthreads();

    float2 bb = *(const float2*)(bias + tid * 2);
    float2 rt = __half22float2(__ldg((const __half2*)(Y + (size_t)dst * 2304 + 2048) + tid));
    float2 acc = make_float2(rt.x + bb.x, rt.y + bb.y);

    int e = s;
    for (; e + 4 <= t; e += 4) {
        unsigned p0 = csr[e], p1 = csr[e + 1], p2 = csr[e + 2], p3 = csr[e + 3];
        __half2 y0 = __ldg((const __half2*)(Y + (size_t)(p0 & 0xFFFFu) * 2304 + (p0 >> 16) * 256) + tid);
        __half2 y1 = __ldg((const __half2*)(Y + (size_t)(p1 & 0xFFFFu) * 2304 + (p1 >> 16) * 256) + tid);
        __half2 y2 = __ldg((const __half2*)(Y + (size_t)(p2 & 0xFFFFu) * 2304 + (p2 >> 16) * 256) + tid);
        __half2 y3 = __ldg((const __half2*)(Y + (size_t)(p3 & 0xFFFFu) * 2304 + (p3 >> 16) * 256) + tid);
        float2 f0 = __half22float2(y0), f1 = __half22float2(y1);
        float2 f2 = __half22float2(y2), f3 = __half22float2(y3);
        float n0 = nrm[p0 >> 16], n1 = nrm[p1 >> 16], n2 = nrm[p2 >> 16], n3 = nrm[p3 >> 16];
        acc.x += f0.x * n0 + f1.x * n1 + f2.x * n2 + f3.x * n3;
        acc.y += f0.y * n0 + f1.y * n1 + f2.y * n2 + f3.y * n3;
    }
    for (; e < t; e++) {
        unsigned p = csr[e];
        __half2 y = __ldg((const __half2*)(Y + (size_t)(p & 0xFFFFu) * 2304 + (p >> 16) * 256) + tid);
        float2 f = __half22float2(y);
        float n = nrm[p >> 16];
        acc.x += f.x * n;
        acc.y += f.y * n;
    }

    acc.x = fmaxf(acc.x, 0.f);
    acc.y = fmaxf(acc.y, 0.f);
    __nv_bfloat16 h0 = __float2bfloat16(acc.x);
    __nv_bfloat16 h1 = __float2bfloat16(acc.y);
    __nv_bfloat16 l0 = __float2bfloat16(acc.x - __bfloat162float(h0));
    __nv_bfloat16 l1 = __float2bfloat16(acc.y - __bfloat162float(h1));
    uint32_t ph = (uint32_t)__bfloat16_as_ushort(h0) | ((uint32_t)__bfloat16_as_ushort(h1) << 16);
    uint32_t pl = (uint32_t)__bfloat16_as_ushort(l0) | ((uint32_t)__bfloat16_as_ushort(l1) << 16);
    *(uint32_t*)(hh + (size_t)dst * 256 + tid * 2) = ph;
    *(uint32_t*)(hl + (size_t)dst * 256 + tid * 2) = pl;
}

// Layer 2: out = root(from Y2ext) + bias + messages. 64 thr.
__global__ void __launch_bounds__(64)
gather2_kernel(const __half* __restrict__ Y,
               const unsigned* __restrict__ csr,
               const int* __restrict__ offs,
               const int* __restrict__ cnt,
               const float* __restrict__ bias,
               float* __restrict__ out)
{
    const int dst = blockIdx.x;
    const int tid = threadIdx.x;
    __shared__ float nrm[8];
    if (tid < 8) nrm[tid] = 1.0f / (float)max(cnt[dst * RELS + tid], 1);
    const int s = offs[dst], t = offs[dst + 1];
    __syncthreads();

    float2 bb = *(const float2*)(bias + tid * 2);
    float2 rt = __half22float2(__ldg((const __half2*)(Y + (size_t)dst * 1152 + 1024) + tid));
    float2 acc = make_float2(rt.x + bb.x, rt.y + bb.y);

    int e = s;
    for (; e + 4 <= t; e += 4) {
        unsigned p0 = csr[e], p1 = csr[e + 1], p2 = csr[e + 2], p3 = csr[e + 3];
        __half2 y0 = __ldg((const __half2*)(Y + (size_t)(p0 & 0xFFFFu) * 1152 + (p0 >> 16) * 128) + tid);
        __half2 y1 = __ldg((const __half2*)(Y + (size_t)(p1 & 0xFFFFu) * 1152 + (p1 >> 16) * 128) + tid);
        __half2 y2 = __ldg((const __half2*)(Y + (size_t)(p2 & 0xFFFFu) * 1152 + (p2 >> 16) * 128) + tid);
        __half2 y3 = __ldg((const __half2*)(Y + (size_t)(p3 & 0xFFFFu) * 1152 + (p3 >> 16) * 128) + tid);
        float2 f0 = __half22float2(y0), f1 = __half22float2(y1);
        float2 f2 = __half22float2(y2), f3 = __half22float2(y3);
        float n0 = nrm[p0 >> 16], n1 = nrm[p1 >> 16], n2 = nrm[p2 >> 16], n3 = nrm[p3 >> 16];
        acc.x += f0.x * n0 + f1.x * n1 + f2.x * n2 + f3.x * n3;
        acc.y += f0.y * n0 + f1.y * n1 + f2.y * n2 + f3.y * n3;
    }
    for (; e < t; e++) {
        unsigned p = csr[e];
        __half2 y = __ldg((const __half2*)(Y + (size_t)(p & 0xFFFFu) * 1152 + (p >> 16) * 128) + tid);
        float2 f = __half22float2(y);
        float n = nrm[p >> 16];
        acc.x += f.x * n;
        acc.y += f.y * n;
    }
    *(float2*)(out + (size_t)dst * 128 + tid * 2) = acc;
}

// ---------------------------------------------------------------------------
extern "C" void kernel_launch(void* const* d_in, const int* in_sizes, int n_in,
                              void* d_out, int out_size)
{
    const float* x     = (const float*)d_in[0];
    const int*   ei    = (const int*)d_in[1];
    const int*   et    = (const int*)d_in[2];
    const float* W1    = (const float*)d_in[3];
    const float* root1 = (const float*)d_in[4];
    const float* b1    = (const float*)d_in[5];
    const float* W2    = (const float*)d_in[6];
    const float* root2 = (const float*)d_in[7];
    const float* b2    = (const float*)d_in[8];
    float*       out   = (float*)d_out;

    const int N = in_sizes[0] / 256;
    const int E = in_sizes[2];

    __half *Y1, *Y2;
    int *cnt, *deg, *offs, *cur;
    unsigned* csr;
    cudaGetSymbolAddress((void**)&Y1, g_Y1);
    cudaGetSymbolAddress((void**)&Y2, g_Y2);
    cudaGetSymbolAddress((void**)&cnt, g_cnt);
    cudaGetSymbolAddress((void**)&deg, g_deg);
    cudaGetSymbolAddress((void**)&offs, g_offs);
    cudaGetSymbolAddress((void**)&cur, g_cur);
    cudaGetSymbolAddress((void**)&csr, g_csr);
    __nv_bfloat16 *xh, *xl, *hh, *hl, *w1h, *w1l, *w2h, *w2l;
    cudaGetSymbolAddress((void**)&xh, g_xh);
    cudaGetSymbolAddress((void**)&xl, g_xl);
    cudaGetSymbolAddress((void**)&hh, g_hh);
    cudaGetSymbolAddress((void**)&hl, g_hl);
    cudaGetSymbolAddress((void**)&w1h, g_w1h);
    cudaGetSymbolAddress((void**)&w1l, g_w1l);
    cudaGetSymbolAddress((void**)&w2h, g_w2h);
    cudaGetSymbolAddress((void**)&w2l, g_w2l);

    static int attr_set = 0;
    if (!attr_set) {
        cudaFuncSetAttribute(gemm_pipe, cudaFuncAttributeMaxDynamicSharedMemorySize, SMEMP);
        attr_set = 1;
    }

    // ---- CSR build ----
    zero_int_kernel<<<(N * RELS + 255) / 256, 256>>>(cnt, N * RELS);
    zero_int_kernel<<<(N + 255) / 256, 256>>>(cur, N);
    count_kernel<<<(E + 255) / 256, 256>>>(ei, et, cnt, E);
    deg_kernel<<<(N + 255) / 256, 256>>>(cnt, deg, N);
    scan_kernel<<<1, 1024>>>(deg, offs, N);
    fill_kernel<<<(E + 255) / 256, 256>>>(ei, et, offs, cur, csr, E);

    // ---- weight prep: relations then root appended ----
    convw_kernel<<<(8 * 256 * 256 + 255) / 256, 256>>>(W1, w1h, w1l, 256, 8 * 256 * 256);
    convw_kernel<<<(256 * 256 + 255) / 256, 256>>>(root1, w1h + 2048 * 256, w1l + 2048 * 256, 256, 256 * 256);
    convw_kernel<<<(8 * 256 * 128 + 255) / 256, 256>>>(W2, w2h, w2l, 128, 8 * 256 * 128);
    convw_kernel<<<(256 * 128 + 255) / 256, 256>>>(root2, w2h + 1024 * 256, w2l + 1024 * 256, 128, 256 * 128);
    split_kernel<<<(int)(((size_t)N * 256 + 255) / 256), 256>>>(x, xh, xl, (size_t)N * 256);

    const int mtiles = (N + 127) / 128;

    // ---- layer 1: 18 n-tiles (8 rel x 2 + root x 2) ----
    gemm_pipe<<<dim3(mtiles, 18), 256, SMEMP>>>(xh, xl, N, w1h, w1l, Y1, 2304);
    gather1_kernel<<<N, 128>>>(Y1, csr, offs, cnt, b1, hh, hl);

    // ---- layer 2: 9 n-tiles (8 rel + root) ----
    gemm_pipe<<<dim3(mtiles, 9), 256, SMEMP>>>(hh, hl, N, w2h, w2l, Y2, 1152);
    gather2_kernel<<<N, 64>>>(Y2, csr, offs, cnt, b2, out);
}

// round 9
// speedup vs baseline: 1.1076x; 1.1076x over previous
#include <cuda_runtime.h>
#include <cuda_bf16.h>
#include <cuda_fp16.h>
#include <cstdint>

// ============================================================================
// RGCN 2-layer, transform-first. Root GEMM fused as a 9th relation.
// GEMMs: mma.sync bf16 2-way split (hi*hi + hi*lo + lo*hi), 2-stage cp.async
// (R7-proven loop). Messages+root fp16. CSR pull aggregation, bias in gather.
// ============================================================================

#define MAXN 50000
#define MAXE 840000
#define RELS 8

__device__ __half g_Y1[(size_t)MAXN * 2304];   // [N, 8*256 + 256(root)]
__device__ __half g_Y2[(size_t)MAXN * 1152];   // [N, 8*128 + 128(root)]
__device__ int    g_cnt[MAXN * RELS];
__device__ int    g_deg[MAXN];
__device__ int    g_offs[MAXN + 1];
__device__ int    g_cur[MAXN];
__device__ unsigned g_csr[MAXE];

__device__ __nv_bfloat16 g_xh[(size_t)MAXN * 256];
__device__ __nv_bfloat16 g_xl[(size_t)MAXN * 256];
__device__ __nv_bfloat16 g_hh[(size_t)MAXN * 256];
__device__ __nv_bfloat16 g_hl[(size_t)MAXN * 256];

__device__ __nv_bfloat16 g_w1h[2304 * 256], g_w1l[2304 * 256];
__device__ __nv_bfloat16 g_w2h[1152 * 256], g_w2l[1152 * 256];

// ---------------------------------------------------------------------------
__device__ __forceinline__ void ldsm4(uint32_t* r, uint32_t addr)
{
    asm volatile("ldmatrix.sync.aligned.m8n8.x4.shared.b16 {%0,%1,%2,%3}, [%4];"
                 : "=r"(r[0]), "=r"(r[1]), "=r"(r[2]), "=r"(r[3]) : "r"(addr));
}

__device__ __forceinline__ void mma_bf16(float* c, const uint32_t* a, const uint32_t* b)
{
    asm volatile(
        "mma.sync.aligned.m16n8k16.row.col.f32.bf16.bf16.f32 "
        "{%0,%1,%2,%3}, {%4,%5,%6,%7}, {%8,%9}, {%0,%1,%2,%3};"
        : "+f"(c[0]), "+f"(c[1]), "+f"(c[2]), "+f"(c[3])
        : "r"(a[0]), "r"(a[1]), "r"(a[2]), "r"(a[3]), "r"(b[0]), "r"(b[1]));
}

#define CP_COMMIT() asm volatile("cp.async.commit_group;" ::: "memory")
#define CP_WAIT1()  asm volatile("cp.async.wait_group 1;" ::: "memory")
#define CP_WAIT0()  asm volatile("cp.async.wait_group 0;" ::: "memory")

__device__ __forceinline__ void cp16(uint32_t dst, const void* src, int sz)
{
    asm volatile("cp.async.ca.shared.global [%0], [%1], 16, %2;"
                 :: "r"(dst), "l"(src), "r"(sz));
}

// ---------------------------------------------------------------------------
// Pipelined GEMM (R7 loop): C[M,T] = A[M,256] @ Bt[T,256]^T, fp16 out.
// CTA 128x128, 8 warps (2x4 of 64x32), kc=32, 2-stage cp.async, 2 syncs/iter.
// ---------------------------------------------------------------------------
#define OP_BYTES 10240
#define STG_BYTES 40960
#define SMEMP (2 * STG_BYTES)

__global__ void __launch_bounds__(256)
gemm_pipe(const __nv_bfloat16* __restrict__ Ah, const __nv_bfloat16* __restrict__ Al,
          int M,
          const __nv_bfloat16* __restrict__ Bh, const __nv_bfloat16* __restrict__ Bl,
          __half* __restrict__ C, int ldc)
{
    extern __shared__ char smem[];
    uint32_t sb0;
    asm("{ .reg .u64 t; cvta.to.shared.u64 t, %1; cvt.u32.u64 %0, t; }"
        : "=r"(sb0) : "l"(smem));

    const int tid  = threadIdx.x;
    const int wid  = tid >> 5;
    const int lane = tid & 31;
    const int wm   = wid >> 2;
    const int wn   = wid & 3;
    const int bm   = blockIdx.x * 128;
    const int bn   = blockIdx.y * 128;

    float acc[4][4][4];
#pragma unroll
    for (int i = 0; i < 4; i++)
#pragma unroll
        for (int j = 0; j < 4; j++)
#pragma unroll
            for (int q = 0; q < 4; q++) acc[i][j][q] = 0.f;

    const int q8 = lane >> 3;
    const int lg = lane & 7;

    auto load_stage = [&](int stage, int k0) {
        uint32_t sb = sb0 + stage * STG_BYTES;
#pragma unroll
        for (int i = 0; i < 8; i++) {
            int c   = tid + i * 256;
            int op  = i >> 1;
            int idx = c & 511;
            int row = idx >> 2;
            int seg = (idx & 3) * 8;
            const __nv_bfloat16* g;
            int grow;
            int sz = 16;
            if (op == 0)      { g = Ah; grow = bm + row; if (grow >= M) { grow = 0; sz = 0; } }
            else if (op == 1) { g = Al; grow = bm + row; if (grow >= M) { grow = 0; sz = 0; } }
            else if (op == 2) { g = Bh; grow = bn + row; }
            else              { g = Bl; grow = bn + row; }
            cp16(sb + op * OP_BYTES + row * 80 + seg * 2,
                 g + (size_t)grow * 256 + k0 + seg, sz);
        }
        CP_COMMIT();
    };

    load_stage(0, 0);

    for (int kb = 0; kb < 8; kb++) {
        if (kb < 7) load_stage((kb + 1) & 1, (kb + 1) * 32);
        if (kb < 7) CP_WAIT1(); else CP_WAIT0();
        __syncthreads();

        const uint32_t sb = sb0 + (kb & 1) * STG_BYTES;
        const uint32_t sAh_b = sb;
        const uint32_t sAl_b = sb + OP_BYTES;
        const uint32_t sBh_b = sb + 2 * OP_BYTES;
        const uint32_t sBl_b = sb + 3 * OP_BYTES;

#pragma unroll
        for (int ks = 0; ks < 2; ks++) {
            uint32_t bh[8], bl[8];
#pragma unroll
            for (int np = 0; np < 2; np++) {
                int nrow = wn * 32 + np * 16 + lg + ((q8 >> 1) ? 8 : 0);
                int bcol = ks * 32 + ((q8 & 1) ? 16 : 0);
                ldsm4(&bh[np * 4], sBh_b + nrow * 80 + bcol);
                ldsm4(&bl[np * 4], sBl_b + nrow * 80 + bcol);
            }
#pragma unroll
            for (int mt = 0; mt < 4; mt++) {
                int arow = wm * 64 + mt * 16 + lg + ((q8 & 1) ? 8 : 0);
                int acol = ks * 32 + ((q8 >> 1) ? 16 : 0);
                uint32_t ah[4], al[4];
                ldsm4(ah, sAh_b + arow * 80 + acol);
                ldsm4(al, sAl_b + arow * 80 + acol);
#pragma unroll
                for (int nt = 0; nt < 4; nt++) mma_bf16(acc[mt][nt], ah, &bh[nt * 2]);
#pragma unroll
                for (int nt = 0; nt < 4; nt++) mma_bf16(acc[mt][nt], ah, &bl[nt * 2]);
#pragma unroll
                for (int nt = 0; nt < 4; nt++) mma_bf16(acc[mt][nt], al, &bh[nt * 2]);
            }
        }
        __syncthreads();
    }

    // ---- epilogue (fp16) ----
#pragma unroll
    for (int mt = 0; mt < 4; mt++) {
#pragma unroll
        for (int nt = 0; nt < 4; nt++) {
            int gr0  = bm + wm * 64 + mt * 16 + (lane >> 2);
            int gcol = bn + wn * 32 + nt * 8 + (lane & 3) * 2;
#pragma unroll
            for (int h = 0; h < 2; h++) {
                int gr = gr0 + h * 8;
                if (gr < M) {
                    *(__half2*)(C + (size_t)gr * ldc + gcol) =
                        __floats2half2_rn(acc[mt][nt][h * 2 + 0], acc[mt][nt][h * 2 + 1]);
                }
            }
        }
    }
}

// ---------------------------------------------------------------------------
// Prep kernels
// ---------------------------------------------------------------------------
__global__ void convw_kernel(const float* __restrict__ W,
                             __nv_bfloat16* __restrict__ hi,
                             __nv_bfloat16* __restrict__ lo,
                             int N, int total)
{
    int idx = blockIdx.x * blockDim.x + threadIdx.x;
    if (idx >= total) return;
    int n = idx % N;
    int k = (idx / N) & 255;
    int r = idx / (N * 256);
    float f = W[idx];
    __nv_bfloat16 h = __float2bfloat16(f);
    __nv_bfloat16 l = __float2bfloat16(f - __bfloat162float(h));
    size_t o = ((size_t)r * N + n) * 256 + k;
    hi[o] = h;
    lo[o] = l;
}

__global__ void split_kernel(const float* __restrict__ X,
                             __nv_bfloat16* __restrict__ hi,
                             __nv_bfloat16* __restrict__ lo,
                             size_t total)
{
    size_t i = (size_t)blockIdx.x * blockDim.x + threadIdx.x;
    if (i >= total) return;
    float f = X[i];
    __nv_bfloat16 h = __float2bfloat16(f);
    hi[i] = h;
    lo[i] = __float2bfloat16(f - __bfloat162float(h));
}

// ---------------------------------------------------------------------------
// CSR construction
// ---------------------------------------------------------------------------
__global__ void zero_int_kernel(int* p, int n)
{
    int i = blockIdx.x * blockDim.x + threadIdx.x;
    if (i < n) p[i] = 0;
}

__global__ void count_kernel(const int* __restrict__ ei,
                             const int* __restrict__ et,
                             int* __restrict__ cnt, int E)
{
    int e = blockIdx.x * blockDim.x + threadIdx.x;
    if (e < E) atomicAdd(&cnt[ei[E + e] * RELS + et[e]], 1);
}

__global__ void deg_kernel(const int* __restrict__ cnt, int* __restrict__ deg, int n)
{
    int i = blockIdx.x * blockDim.x + threadIdx.x;
    if (i < n) {
        int s = 0;
#pragma unroll
        for (int r = 0; r < RELS; r++) s += cnt[i * RELS + r];
        deg[i] = s;
    }
}

__global__ void scan_kernel(const int* __restrict__ deg, int* __restrict__ offs, int n)
{
    __shared__ int buf[1024];
    __shared__ int carry;
    const int tid = threadIdx.x;
    if (tid == 0) carry = 0;
    __syncthreads();
    for (int base = 0; base < n; base += 1024) {
        int i = base + tid;
        int v = (i < n) ? deg[i] : 0;
        buf[tid] = v;
        __syncthreads();
        for (int d = 1; d < 1024; d <<= 1) {
            int t = (tid >= d) ? buf[tid - d] : 0;
            __syncthreads();
            buf[tid] += t;
            __syncthreads();
        }
        if (i < n) offs[i] = carry + buf[tid] - v;
        __syncthreads();
        if (tid == 0) carry += buf[1023];
        __syncthreads();
    }
    if (tid == 0) offs[n] = carry;
}

__global__ void fill_kernel(const int* __restrict__ ei,
                            const int* __restrict__ et,
                            const int* __restrict__ offs,
                            int* __restrict__ cur,
                            unsigned* __restrict__ csr, int E)
{
    int e = blockIdx.x * blockDim.x + threadIdx.x;
    if (e < E) {
        int d = ei[E + e];
        int pos = offs[d] + atomicAdd(&cur[d], 1);
        csr[pos] = (unsigned)ei[e] | ((unsigned)et[e] << 16);
    }
}

// ---------------------------------------------------------------------------
// Gather. Layer 1: root(from Y1ext)+bias+messages, relu, bf16 split. 128 thr.
// ---------------------------------------------------------------------------
__global__ void __launch_bounds__(128)
gather1_kernel(const __half* __restrict__ Y,
               const unsigned* __restrict__ csr,
               const int* __restrict__ offs,
               const int* __restrict__ cnt,
               const float* __restrict__ bias,
               __nv_bfloat16* __restrict__ hh,
               __nv_bfloat16* __restrict__ hl)
{
    const int dst = blockIdx.x;
    const int tid = threadIdx.x;
    __shared__ float nrm[8];
    if (tid < 8) nrm[tid] = 1.0f / (float)max(cnt[dst * RELS + tid], 1);
    const int s = offs[dst], t = offs[dst + 1];
    __syncthreads();

    float2 bb = *(const float2*)(bias + tid * 2);
    float2 rt = __half22float2(__ldg((const __half2*)(Y + (size_t)dst * 2304 + 2048) + tid));
    float2 acc = make_float2(rt.x + bb.x, rt.y + bb.y);

    int e = s;
    for (; e + 4 <= t; e += 4) {
        unsigned p0 = csr[e], p1 = csr[e + 1], p2 = csr[e + 2], p3 = csr[e + 3];
        __half2 y0 = __ldg((const __half2*)(Y + (size_t)(p0 & 0xFFFFu) * 2304 + (p0 >> 16) * 256) + tid);
        __half2 y1 = __ldg((const __half2*)(Y + (size_t)(p1 & 0xFFFFu) * 2304 + (p1 >> 16) * 256) + tid);
        __half2 y2 = __ldg((const __half2*)(Y + (size_t)(p2 & 0xFFFFu) * 2304 + (p2 >> 16) * 256) + tid);
        __half2 y3 = __ldg((const __half2*)(Y + (size_t)(p3 & 0xFFFFu) * 2304 + (p3 >> 16) * 256) + tid);
        float2 f0 = __half22float2(y0), f1 = __half22float2(y1);
        float2 f2 = __half22float2(y2), f3 = __half22float2(y3);
        float n0 = nrm[p0 >> 16], n1 = nrm[p1 >> 16], n2 = nrm[p2 >> 16], n3 = nrm[p3 >> 16];
        acc.x += f0.x * n0 + f1.x * n1 + f2.x * n2 + f3.x * n3;
        acc.y += f0.y * n0 + f1.y * n1 + f2.y * n2 + f3.y * n3;
    }
    for (; e < t; e++) {
        unsigned p = csr[e];
        __half2 y = __ldg((const __half2*)(Y + (size_t)(p & 0xFFFFu) * 2304 + (p >> 16) * 256) + tid);
        float2 f = __half22float2(y);
        float n = nrm[p >> 16];
        acc.x += f.x * n;
        acc.y += f.y * n;
    }

    acc.x = fmaxf(acc.x, 0.f);
    acc.y = fmaxf(acc.y, 0.f);
    __nv_bfloat16 h0 = __float2bfloat16(acc.x);
    __nv_bfloat16 h1 = __float2bfloat16(acc.y);
    __nv_bfloat16 l0 = __float2bfloat16(acc.x - __bfloat162float(h0));
    __nv_bfloat16 l1 = __float2bfloat16(acc.y - __bfloat162float(h1));
    uint32_t ph = (uint32_t)__bfloat16_as_ushort(h0) | ((uint32_t)__bfloat16_as_ushort(h1) << 16);
    uint32_t pl = (uint32_t)__bfloat16_as_ushort(l0) | ((uint32_t)__bfloat16_as_ushort(l1) << 16);
    *(uint32_t*)(hh + (size_t)dst * 256 + tid * 2) = ph;
    *(uint32_t*)(hl + (size_t)dst * 256 + tid * 2) = pl;
}

// Layer 2: out = root(from Y2ext) + bias + messages. 64 thr.
__global__ void __launch_bounds__(64)
gather2_kernel(const __half* __restrict__ Y,
               const unsigned* __restrict__ csr,
               const int* __restrict__ offs,
               const int* __restrict__ cnt,
               const float* __restrict__ bias,
               float* __restrict__ out)
{
    const int dst = blockIdx.x;
    const int tid = threadIdx.x;
    __shared__ float nrm[8];
    if (tid < 8) nrm[tid] = 1.0f / (float)max(cnt[dst * RELS + tid], 1);
    const int s = offs[dst], t = offs[dst + 1];
    __syncthreads();

    float2 bb = *(const float2*)(bias + tid * 2);
    float2 rt = __half22float2(__ldg((const __half2*)(Y + (size_t)dst * 1152 + 1024) + tid));
    float2 acc = make_float2(rt.x + bb.x, rt.y + bb.y);

    int e = s;
    for (; e + 4 <= t; e += 4) {
        unsigned p0 = csr[e], p1 = csr[e + 1], p2 = csr[e + 2], p3 = csr[e + 3];
        __half2 y0 = __ldg((const __half2*)(Y + (size_t)(p0 & 0xFFFFu) * 1152 + (p0 >> 16) * 128) + tid);
        __half2 y1 = __ldg((const __half2*)(Y + (size_t)(p1 & 0xFFFFu) * 1152 + (p1 >> 16) * 128) + tid);
        __half2 y2 = __ldg((const __half2*)(Y + (size_t)(p2 & 0xFFFFu) * 1152 + (p2 >> 16) * 128) + tid);
        __half2 y3 = __ldg((const __half2*)(Y + (size_t)(p3 & 0xFFFFu) * 1152 + (p3 >> 16) * 128) + tid);
        float2 f0 = __half22float2(y0), f1 = __half22float2(y1);
        float2 f2 = __half22float2(y2), f3 = __half22float2(y3);
        float n0 = nrm[p0 >> 16], n1 = nrm[p1 >> 16], n2 = nrm[p2 >> 16], n3 = nrm[p3 >> 16];
        acc.x += f0.x * n0 + f1.x * n1 + f2.x * n2 + f3.x * n3;
        acc.y += f0.y * n0 + f1.y * n1 + f2.y * n2 + f3.y * n3;
    }
    for (; e < t; e++) {
        unsigned p = csr[e];
        __half2 y = __ldg((const __half2*)(Y + (size_t)(p & 0xFFFFu) * 1152 + (p >> 16) * 128) + tid);
        float2 f = __half22float2(y);
        float n = nrm[p >> 16];
        acc.x += f.x * n;
        acc.y += f.y * n;
    }
    *(float2*)(out + (size_t)dst * 128 + tid * 2) = acc;
}

// ---------------------------------------------------------------------------
extern "C" void kernel_launch(void* const* d_in, const int* in_sizes, int n_in,
                              void* d_out, int out_size)
{
    const float* x     = (const float*)d_in[0];
    const int*   ei    = (const int*)d_in[1];
    const int*   et    = (const int*)d_in[2];
    const float* W1    = (const float*)d_in[3];
    const float* root1 = (const float*)d_in[4];
    const float* b1    = (const float*)d_in[5];
    const float* W2    = (const float*)d_in[6];
    const float* root2 = (const float*)d_in[7];
    const float* b2    = (const float*)d_in[8];
    float*       out   = (float*)d_out;

    const int N = in_sizes[0] / 256;
    const int E = in_sizes[2];

    __half *Y1, *Y2;
    int *cnt, *deg, *offs, *cur;
    unsigned* csr;
    cudaGetSymbolAddress((void**)&Y1, g_Y1);
    cudaGetSymbolAddress((void**)&Y2, g_Y2);
    cudaGetSymbolAddress((void**)&cnt, g_cnt);
    cudaGetSymbolAddress((void**)&deg, g_deg);
    cudaGetSymbolAddress((void**)&offs, g_offs);
    cudaGetSymbolAddress((void**)&cur, g_cur);
    cudaGetSymbolAddress((void**)&csr, g_csr);
    __nv_bfloat16 *xh, *xl, *hh, *hl, *w1h, *w1l, *w2h, *w2l;
    cudaGetSymbolAddress((void**)&xh, g_xh);
    cudaGetSymbolAddress((void**)&xl, g_xl);
    cudaGetSymbolAddress((void**)&hh, g_hh);
    cudaGetSymbolAddress((void**)&hl, g_hl);
    cudaGetSymbolAddress((void**)&w1h, g_w1h);
    cudaGetSymbolAddress((void**)&w1l, g_w1l);
    cudaGetSymbolAddress((void**)&w2h, g_w2h);
    cudaGetSymbolAddress((void**)&w2l, g_w2l);

    static int attr_set = 0;
    if (!attr_set) {
        cudaFuncSetAttribute(gemm_pipe, cudaFuncAttributeMaxDynamicSharedMemorySize, SMEMP);
        attr_set = 1;
    }

    // ---- CSR build ----
    zero_int_kernel<<<(N * RELS + 255) / 256, 256>>>(cnt, N * RELS);
    zero_int_kernel<<<(N + 255) / 256, 256>>>(cur, N);
    count_kernel<<<(E + 255) / 256, 256>>>(ei, et, cnt, E);
    deg_kernel<<<(N + 255) / 256, 256>>>(cnt, deg, N);
    scan_kernel<<<1, 1024>>>(deg, offs, N);
    fill_kernel<<<(E + 255) / 256, 256>>>(ei, et, offs, cur, csr, E);

    // ---- weight prep: relations then root appended ----
    convw_kernel<<<(8 * 256 * 256 + 255) / 256, 256>>>(W1, w1h, w1l, 256, 8 * 256 * 256);
    convw_kernel<<<(256 * 256 + 255) / 256, 256>>>(root1, w1h + 2048 * 256, w1l + 2048 * 256, 256, 256 * 256);
    convw_kernel<<<(8 * 256 * 128 + 255) / 256, 256>>>(W2, w2h, w2l, 128, 8 * 256 * 128);
    convw_kernel<<<(256 * 128 + 255) / 256, 256>>>(root2, w2h + 1024 * 256, w2l + 1024 * 256, 128, 256 * 128);
    split_kernel<<<(int)(((size_t)N * 256 + 255) / 256), 256>>>(x, xh, xl, (size_t)N * 256);

    const int mtiles = (N + 127) / 128;

    // ---- layer 1: 18 n-tiles (8 rel x 2 + root x 2) ----
    gemm_pipe<<<dim3(mtiles, 18), 256, SMEMP>>>(xh, xl, N, w1h, w1l, Y1, 2304);
    gather1_kernel<<<N, 128>>>(Y1, csr, offs, cnt, b1, hh, hl);

    // ---- layer 2: 9 n-tiles (8 rel + root) ----
    gemm_pipe<<<dim3(mtiles, 9), 256, SMEMP>>>(hh, hl, N, w2h, w2l, Y2, 1152);
    gather2_kernel<<<N, 64>>>(Y2, csr, offs, cnt, b2, out);
}

// round 10
// speedup vs baseline: 1.1997x; 1.0831x over previous
#include <cuda_runtime.h>
#include <cuda_bf16.h>
#include <cuda_fp16.h>
#include <cstdint>

// ============================================================================
// RGCN 2-layer, transform-first. Root GEMM fused as a 9th relation.
// GEMMs: mma.sync bf16 2-way split, 2-stage cp.async (R7 loop).
// Messages+root fp16. CSR pull aggregation. CSR build forked onto a side
// stream (event-based capture fork) to overlap with prep+GEMM1.
// ============================================================================

#define MAXN 50000
#define MAXE 840000
#define RELS 8

__device__ __half g_Y1[(size_t)MAXN * 2304];   // [N, 8*256 + 256(root)]
__device__ __half g_Y2[(size_t)MAXN * 1152];   // [N, 8*128 + 128(root)]
__device__ int    g_cnt[MAXN * RELS];
__device__ int    g_deg[MAXN];
__device__ int    g_offs[MAXN + 1];
__device__ int    g_cur[MAXN];
__device__ unsigned g_csr[MAXE];

__device__ __nv_bfloat16 g_xh[(size_t)MAXN * 256];
__device__ __nv_bfloat16 g_xl[(size_t)MAXN * 256];
__device__ __nv_bfloat16 g_hh[(size_t)MAXN * 256];
__device__ __nv_bfloat16 g_hl[(size_t)MAXN * 256];

__device__ __nv_bfloat16 g_w1h[2304 * 256], g_w1l[2304 * 256];
__device__ __nv_bfloat16 g_w2h[1152 * 256], g_w2l[1152 * 256];

// ---------------------------------------------------------------------------
__device__ __forceinline__ void ldsm4(uint32_t* r, uint32_t addr)
{
    asm volatile("ldmatrix.sync.aligned.m8n8.x4.shared.b16 {%0,%1,%2,%3}, [%4];"
                 : "=r"(r[0]), "=r"(r[1]), "=r"(r[2]), "=r"(r[3]) : "r"(addr));
}

__device__ __forceinline__ void mma_bf16(float* c, const uint32_t* a, const uint32_t* b)
{
    asm volatile(
        "mma.sync.aligned.m16n8k16.row.col.f32.bf16.bf16.f32 "
        "{%0,%1,%2,%3}, {%4,%5,%6,%7}, {%8,%9}, {%0,%1,%2,%3};"
        : "+f"(c[0]), "+f"(c[1]), "+f"(c[2]), "+f"(c[3])
        : "r"(a[0]), "r"(a[1]), "r"(a[2]), "r"(a[3]), "r"(b[0]), "r"(b[1]));
}

#define CP_COMMIT() asm volatile("cp.async.commit_group;" ::: "memory")
#define CP_WAIT1()  asm volatile("cp.async.wait_group 1;" ::: "memory")
#define CP_WAIT0()  asm volatile("cp.async.wait_group 0;" ::: "memory")

__device__ __forceinline__ void cp16(uint32_t dst, const void* src, int sz)
{
    asm volatile("cp.async.ca.shared.global [%0], [%1], 16, %2;"
                 :: "r"(dst), "l"(src), "r"(sz));
}

// ---------------------------------------------------------------------------
// Pipelined GEMM (R7 loop): C[M,T] = A[M,256] @ Bt[T,256]^T, fp16 out.
// CTA 128x128, 8 warps (2x4 of 64x32), kc=32, 2-stage cp.async, 2 syncs/iter.
// ---------------------------------------------------------------------------
#define OP_BYTES 10240
#define STG_BYTES 40960
#define SMEMP (2 * STG_BYTES)

__global__ void __launch_bounds__(256)
gemm_pipe(const __nv_bfloat16* __restrict__ Ah, const __nv_bfloat16* __restrict__ Al,
          int M,
          const __nv_bfloat16* __restrict__ Bh, const __nv_bfloat16* __restrict__ Bl,
          __half* __restrict__ C, int ldc)
{
    extern __shared__ char smem[];
    uint32_t sb0;
    asm("{ .reg .u64 t; cvta.to.shared.u64 t, %1; cvt.u32.u64 %0, t; }"
        : "=r"(sb0) : "l"(smem));

    const int tid  = threadIdx.x;
    const int wid  = tid >> 5;
    const int lane = tid & 31;
    const int wm   = wid >> 2;
    const int wn   = wid & 3;
    const int bm   = blockIdx.x * 128;
    const int bn   = blockIdx.y * 128;

    float acc[4][4][4];
#pragma unroll
    for (int i = 0; i < 4; i++)
#pragma unroll
        for (int j = 0; j < 4; j++)
#pragma unroll
            for (int q = 0; q < 4; q++) acc[i][j][q] = 0.f;

    const int q8 = lane >> 3;
    const int lg = lane & 7;

    auto load_stage = [&](int stage, int k0) {
        uint32_t sb = sb0 + stage * STG_BYTES;
#pragma unroll
        for (int i = 0; i < 8; i++) {
            int c   = tid + i * 256;
            int op  = i >> 1;
            int idx = c & 511;
            int row = idx >> 2;
            int seg = (idx & 3) * 8;
            const __nv_bfloat16* g;
            int grow;
            int sz = 16;
            if (op == 0)      { g = Ah; grow = bm + row; if (grow >= M) { grow = 0; sz = 0; } }
            else if (op == 1) { g = Al; grow = bm + row; if (grow >= M) { grow = 0; sz = 0; } }
            else if (op == 2) { g = Bh; grow = bn + row; }
            else              { g = Bl; grow = bn + row; }
            cp16(sb + op * OP_BYTES + row * 80 + seg * 2,
                 g + (size_t)grow * 256 + k0 + seg, sz);
        }
        CP_COMMIT();
    };

    load_stage(0, 0);

    for (int kb = 0; kb < 8; kb++) {
        if (kb < 7) load_stage((kb + 1) & 1, (kb + 1) * 32);
        if (kb < 7) CP_WAIT1(); else CP_WAIT0();
        __syncthreads();

        const uint32_t sb = sb0 + (kb & 1) * STG_BYTES;
        const uint32_t sAh_b = sb;
        const uint32_t sAl_b = sb + OP_BYTES;
        const uint32_t sBh_b = sb + 2 * OP_BYTES;
        const uint32_t sBl_b = sb + 3 * OP_BYTES;

#pragma unroll
        for (int ks = 0; ks < 2; ks++) {
            uint32_t bh[8], bl[8];
#pragma unroll
            for (int np = 0; np < 2; np++) {
                int nrow = wn * 32 + np * 16 + lg + ((q8 >> 1) ? 8 : 0);
                int bcol = ks * 32 + ((q8 & 1) ? 16 : 0);
                ldsm4(&bh[np * 4], sBh_b + nrow * 80 + bcol);
                ldsm4(&bl[np * 4], sBl_b + nrow * 80 + bcol);
            }
#pragma unroll
            for (int mt = 0; mt < 4; mt++) {
                int arow = wm * 64 + mt * 16 + lg + ((q8 & 1) ? 8 : 0);
                int acol = ks * 32 + ((q8 >> 1) ? 16 : 0);
                uint32_t ah[4], al[4];
                ldsm4(ah, sAh_b + arow * 80 + acol);
                ldsm4(al, sAl_b + arow * 80 + acol);
#pragma unroll
                for (int nt = 0; nt < 4; nt++) mma_bf16(acc[mt][nt], ah, &bh[nt * 2]);
#pragma unroll
                for (int nt = 0; nt < 4; nt++) mma_bf16(acc[mt][nt], ah, &bl[nt * 2]);
#pragma unroll
                for (int nt = 0; nt < 4; nt++) mma_bf16(acc[mt][nt], al, &bh[nt * 2]);
            }
        }
        __syncthreads();
    }

    // ---- epilogue (fp16) ----
#pragma unroll
    for (int mt = 0; mt < 4; mt++) {
#pragma unroll
        for (int nt = 0; nt < 4; nt++) {
            int gr0  = bm + wm * 64 + mt * 16 + (lane >> 2);
            int gcol = bn + wn * 32 + nt * 8 + (lane & 3) * 2;
#pragma unroll
            for (int h = 0; h < 2; h++) {
                int gr = gr0 + h * 8;
                if (gr < M) {
                    *(__half2*)(C + (size_t)gr * ldc + gcol) =
                        __floats2half2_rn(acc[mt][nt][h * 2 + 0], acc[mt][nt][h * 2 + 1]);
                }
            }
        }
    }
}

// ---------------------------------------------------------------------------
// Prep kernels
// ---------------------------------------------------------------------------
__global__ void convw_kernel(const float* __restrict__ W,
                             __nv_bfloat16* __restrict__ hi,
                             __nv_bfloat16* __restrict__ lo,
                             int N, int total)
{
    int idx = blockIdx.x * blockDim.x + threadIdx.x;
    if (idx >= total) return;
    int n = idx % N;
    int k = (idx / N) & 255;
    int r = idx / (N * 256);
    float f = W[idx];
    __nv_bfloat16 h = __float2bfloat16(f);
    __nv_bfloat16 l = __float2bfloat16(f - __bfloat162float(h));
    size_t o = ((size_t)r * N + n) * 256 + k;
    hi[o] = h;
    lo[o] = l;
}

__global__ void split_kernel(const float* __restrict__ X,
                             __nv_bfloat16* __restrict__ hi,
                             __nv_bfloat16* __restrict__ lo,
                             size_t total)
{
    size_t i = (size_t)blockIdx.x * blockDim.x + threadIdx.x;
    if (i >= total) return;
    float f = X[i];
    __nv_bfloat16 h = __float2bfloat16(f);
    hi[i] = h;
    lo[i] = __float2bfloat16(f - __bfloat162float(h));
}

// ---------------------------------------------------------------------------
// CSR construction
// ---------------------------------------------------------------------------
__global__ void zero_int_kernel(int* p, int n)
{
    int i = blockIdx.x * blockDim.x + threadIdx.x;
    if (i < n) p[i] = 0;
}

__global__ void count_kernel(const int* __restrict__ ei,
                             const int* __restrict__ et,
                             int* __restrict__ cnt, int E)
{
    int e = blockIdx.x * blockDim.x + threadIdx.x;
    if (e < E) atomicAdd(&cnt[ei[E + e] * RELS + et[e]], 1);
}

__global__ void deg_kernel(const int* __restrict__ cnt, int* __restrict__ deg, int n)
{
    int i = blockIdx.x * blockDim.x + threadIdx.x;
    if (i < n) {
        int s = 0;
#pragma unroll
        for (int r = 0; r < RELS; r++) s += cnt[i * RELS + r];
        deg[i] = s;
    }
}

__global__ void scan_kernel(const int* __restrict__ deg, int* __restrict__ offs, int n)
{
    __shared__ int buf[1024];
    __shared__ int carry;
    const int tid = threadIdx.x;
    if (tid == 0) carry = 0;
    __syncthreads();
    for (int base = 0; base < n; base += 1024) {
        int i = base + tid;
        int v = (i < n) ? deg[i] : 0;
        buf[tid] = v;
        __syncthreads();
        for (int d = 1; d < 1024; d <<= 1) {
            int t = (tid >= d) ? buf[tid - d] : 0;
            __syncthreads();
            buf[tid] += t;
            __syncthreads();
        }
        if (i < n) offs[i] = carry + buf[tid] - v;
        __syncthreads();
        if (tid == 0) carry += buf[1023];
        __syncthreads();
    }
    if (tid == 0) offs[n] = carry;
}

__global__ void fill_kernel(const int* __restrict__ ei,
                            const int* __restrict__ et,
                            const int* __restrict__ offs,
                            int* __restrict__ cur,
                            unsigned* __restrict__ csr, int E)
{
    int e = blockIdx.x * blockDim.x + threadIdx.x;
    if (e < E) {
        int d = ei[E + e];
        int pos = offs[d] + atomicAdd(&cur[d], 1);
        csr[pos] = (unsigned)ei[e] | ((unsigned)et[e] << 16);
    }
}

// ---------------------------------------------------------------------------
// Gather. Layer 1: root(from Y1ext)+bias+messages, relu, bf16 split. 128 thr.
// ---------------------------------------------------------------------------
__global__ void __launch_bounds__(128)
gather1_kernel(const __half* __restrict__ Y,
               const unsigned* __restrict__ csr,
               const int* __restrict__ offs,
               const int* __restrict__ cnt,
               const float* __restrict__ bias,
               __nv_bfloat16* __restrict__ hh,
               __nv_bfloat16* __restrict__ hl)
{
    const int dst = blockIdx.x;
    const int tid = threadIdx.x;
    __shared__ float nrm[8];
    if (tid < 8) nrm[tid] = 1.0f / (float)max(cnt[dst * RELS + tid], 1);
    const int s = offs[dst], t = offs[dst + 1];
    __syncthreads();

    float2 bb = *(const float2*)(bias + tid * 2);
    float2 rt = __half22float2(__ldg((const __half2*)(Y + (size_t)dst * 2304 + 2048) + tid));
    float2 acc = make_float2(rt.x + bb.x, rt.y + bb.y);

    int e = s;
    for (; e + 4 <= t; e += 4) {
        unsigned p0 = csr[e], p1 = csr[e + 1], p2 = csr[e + 2], p3 = csr[e + 3];
        __half2 y0 = __ldg((const __half2*)(Y + (size_t)(p0 & 0xFFFFu) * 2304 + (p0 >> 16) * 256) + tid);
        __half2 y1 = __ldg((const __half2*)(Y + (size_t)(p1 & 0xFFFFu) * 2304 + (p1 >> 16) * 256) + tid);
        __half2 y2 = __ldg((const __half2*)(Y + (size_t)(p2 & 0xFFFFu) * 2304 + (p2 >> 16) * 256) + tid);
        __half2 y3 = __ldg((const __half2*)(Y + (size_t)(p3 & 0xFFFFu) * 2304 + (p3 >> 16) * 256) + tid);
        float2 f0 = __half22float2(y0), f1 = __half22float2(y1);
        float2 f2 = __half22float2(y2), f3 = __half22float2(y3);
        float n0 = nrm[p0 >> 16], n1 = nrm[p1 >> 16], n2 = nrm[p2 >> 16], n3 = nrm[p3 >> 16];
        acc.x += f0.x * n0 + f1.x * n1 + f2.x * n2 + f3.x * n3;
        acc.y += f0.y * n0 + f1.y * n1 + f2.y * n2 + f3.y * n3;
    }
    for (; e < t; e++) {
        unsigned p = csr[e];
        __half2 y = __ldg((const __half2*)(Y + (size_t)(p & 0xFFFFu) * 2304 + (p >> 16) * 256) + tid);
        float2 f = __half22float2(y);
        float n = nrm[p >> 16];
        acc.x += f.x * n;
        acc.y += f.y * n;
    }

    acc.x = fmaxf(acc.x, 0.f);
    acc.y = fmaxf(acc.y, 0.f);
    __nv_bfloat16 h0 = __float2bfloat16(acc.x);
    __nv_bfloat16 h1 = __float2bfloat16(acc.y);
    __nv_bfloat16 l0 = __float2bfloat16(acc.x - __bfloat162float(h0));
    __nv_bfloat16 l1 = __float2bfloat16(acc.y - __bfloat162float(h1));
    uint32_t ph = (uint32_t)__bfloat16_as_ushort(h0) | ((uint32_t)__bfloat16_as_ushort(h1) << 16);
    uint32_t pl = (uint32_t)__bfloat16_as_ushort(l0) | ((uint32_t)__bfloat16_as_ushort(l1) << 16);
    *(uint32_t*)(hh + (size_t)dst * 256 + tid * 2) = ph;
    *(uint32_t*)(hl + (size_t)dst * 256 + tid * 2) = pl;
}

// Layer 2: out = root(from Y2ext) + bias + messages. 64 thr.
__global__ void __launch_bounds__(64)
gather2_kernel(const __half* __restrict__ Y,
               const unsigned* __restrict__ csr,
               const int* __restrict__ offs,
               const int* __restrict__ cnt,
               const float* __restrict__ bias,
               float* __restrict__ out)
{
    const int dst = blockIdx.x;
    const int tid = threadIdx.x;
    __shared__ float nrm[8];
    if (tid < 8) nrm[tid] = 1.0f / (float)max(cnt[dst * RELS + tid], 1);
    const int s = offs[dst], t = offs[dst + 1];
    __syncthreads();

    float2 bb = *(const float2*)(bias + tid * 2);
    float2 rt = __half22float2(__ldg((const __half2*)(Y + (size_t)dst * 1152 + 1024) + tid));
    float2 acc = make_float2(rt.x + bb.x, rt.y + bb.y);

    int e = s;
    for (; e + 4 <= t; e += 4) {
        unsigned p0 = csr[e], p1 = csr[e + 1], p2 = csr[e + 2], p3 = csr[e + 3];
        __half2 y0 = __ldg((const __half2*)(Y + (size_t)(p0 & 0xFFFFu) * 1152 + (p0 >> 16) * 128) + tid);
        __half2 y1 = __ldg((const __half2*)(Y + (size_t)(p1 & 0xFFFFu) * 1152 + (p1 >> 16) * 128) + tid);
        __half2 y2 = __ldg((const __half2*)(Y + (size_t)(p2 & 0xFFFFu) * 1152 + (p2 >> 16) * 128) + tid);
        __half2 y3 = __ldg((const __half2*)(Y + (size_t)(p3 & 0xFFFFu) * 1152 + (p3 >> 16) * 128) + tid);
        float2 f0 = __half22float2(y0), f1 = __half22float2(y1);
        float2 f2 = __half22float2(y2), f3 = __half22float2(y3);
        float n0 = nrm[p0 >> 16], n1 = nrm[p1 >> 16], n2 = nrm[p2 >> 16], n3 = nrm[p3 >> 16];
        acc.x += f0.x * n0 + f1.x * n1 + f2.x * n2 + f3.x * n3;
        acc.y += f0.y * n0 + f1.y * n1 + f2.y * n2 + f3.y * n3;
    }
    for (; e < t; e++) {
        unsigned p = csr[e];
        __half2 y = __ldg((const __half2*)(Y + (size_t)(p & 0xFFFFu) * 1152 + (p >> 16) * 128) + tid);
        float2 f = __half22float2(y);
        float n = nrm[p >> 16];
        acc.x += f.x * n;
        acc.y += f.y * n;
    }
    *(float2*)(out + (size_t)dst * 128 + tid * 2) = acc;
}

// ---------------------------------------------------------------------------
extern "C" void kernel_launch(void* const* d_in, const int* in_sizes, int n_in,
                              void* d_out, int out_size)
{
    const float* x     = (const float*)d_in[0];
    const int*   ei    = (const int*)d_in[1];
    const int*   et    = (const int*)d_in[2];
    const float* W1    = (const float*)d_in[3];
    const float* root1 = (const float*)d_in[4];
    const float* b1    = (const float*)d_in[5];
    const float* W2    = (const float*)d_in[6];
    const float* root2 = (const float*)d_in[7];
    const float* b2    = (const float*)d_in[8];
    float*       out   = (float*)d_out;

    const int N = in_sizes[0] / 256;
    const int E = in_sizes[2];

    __half *Y1, *Y2;
    int *cnt, *deg, *offs, *cur;
    unsigned* csr;
    cudaGetSymbolAddress((void**)&Y1, g_Y1);
    cudaGetSymbolAddress((void**)&Y2, g_Y2);
    cudaGetSymbolAddress((void**)&cnt, g_cnt);
    cudaGetSymbolAddress((void**)&deg, g_deg);
    cudaGetSymbolAddress((void**)&offs, g_offs);
    cudaGetSymbolAddress((void**)&cur, g_cur);
    cudaGetSymbolAddress((void**)&csr, g_csr);
    __nv_bfloat16 *xh, *xl, *hh, *hl, *w1h, *w1l, *w2h, *w2l;
    cudaGetSymbolAddress((void**)&xh, g_xh);
    cudaGetSymbolAddress((void**)&xl, g_xl);
    cudaGetSymbolAddress((void**)&hh, g_hh);
    cudaGetSymbolAddress((void**)&hl, g_hl);
    cudaGetSymbolAddress((void**)&w1h, g_w1h);
    cudaGetSymbolAddress((void**)&w1l, g_w1l);
    cudaGetSymbolAddress((void**)&w2h, g_w2h);
    cudaGetSymbolAddress((void**)&w2l, g_w2l);

    static cudaStream_t sCsr = nullptr;
    static cudaEvent_t evFork = nullptr, evCsrDone = nullptr;
    static int attr_set = 0;
    if (!attr_set) {
        cudaFuncSetAttribute(gemm_pipe, cudaFuncAttributeMaxDynamicSharedMemorySize, SMEMP);
        cudaStreamCreateWithFlags(&sCsr, cudaStreamNonBlocking);
        cudaEventCreateWithFlags(&evFork, cudaEventDisableTiming);
        cudaEventCreateWithFlags(&evCsrDone, cudaEventDisableTiming);
        attr_set = 1;
    }

    // ---- fork: CSR build on side stream, prep+GEMM1 on main ----
    cudaEventRecord(evFork, 0);
    cudaStreamWaitEvent(sCsr, evFork, 0);

    zero_int_kernel<<<(N * RELS + 255) / 256, 256, 0, sCsr>>>(cnt, N * RELS);
    zero_int_kernel<<<(N + 255) / 256, 256, 0, sCsr>>>(cur, N);
    count_kernel<<<(E + 255) / 256, 256, 0, sCsr>>>(ei, et, cnt, E);
    deg_kernel<<<(N + 255) / 256, 256, 0, sCsr>>>(cnt, deg, N);
    scan_kernel<<<1, 1024, 0, sCsr>>>(deg, offs, N);
    fill_kernel<<<(E + 255) / 256, 256, 0, sCsr>>>(ei, et, offs, cur, csr, E);
    cudaEventRecord(evCsrDone, sCsr);

    // main stream: weight + input prep
    convw_kernel<<<(8 * 256 * 256 + 255) / 256, 256>>>(W1, w1h, w1l, 256, 8 * 256 * 256);
    convw_kernel<<<(256 * 256 + 255) / 256, 256>>>(root1, w1h + 2048 * 256, w1l + 2048 * 256, 256, 256 * 256);
    convw_kernel<<<(8 * 256 * 128 + 255) / 256, 256>>>(W2, w2h, w2l, 128, 8 * 256 * 128);
    convw_kernel<<<(256 * 128 + 255) / 256, 256>>>(root2, w2h + 1024 * 256, w2l + 1024 * 256, 128, 256 * 128);
    split_kernel<<<(int)(((size_t)N * 256 + 255) / 256), 256>>>(x, xh, xl, (size_t)N * 256);

    const int mtiles = (N + 127) / 128;

    // ---- layer 1 ----
    gemm_pipe<<<dim3(mtiles, 18), 256, SMEMP>>>(xh, xl, N, w1h, w1l, Y1, 2304);

    // join: gather1 needs the CSR
    cudaStreamWaitEvent(0, evCsrDone, 0);
    gather1_kernel<<<N, 128>>>(Y1, csr, offs, cnt, b1, hh, hl);

    // ---- layer 2 ----
    gemm_pipe<<<dim3(mtiles, 9), 256, SMEMP>>>(hh, hl, N, w2h, w2l, Y2, 1152);
    gather2_kernel<<<N, 64>>>(Y2, csr, offs, cnt, b2, out);
}

// round 11
// speedup vs baseline: 1.4483x; 1.2072x over previous
#include <cuda_runtime.h>
#include <cuda_bf16.h>
#include <cuda_fp16.h>
#include <cstdint>

// ============================================================================
// RGCN 2-layer, transform-first. Root GEMM fused as a 9th relation.
// GEMMs: mma.sync fp16, x split hi+lo (2 MMA passes), W rounded to fp16 once.
// 2-stage cp.async pipeline. Messages+root fp16. CSR pull aggregation,
// CSR build + W2 prep forked onto a side stream.
// ============================================================================

#define MAXN 50000
#define MAXE 840000
#define RELS 8

__device__ __half g_Y1[(size_t)MAXN * 2304];   // [N, 8*256 + 256(root)]
__device__ __half g_Y2[(size_t)MAXN * 1152];   // [N, 8*128 + 128(root)]
__device__ int    g_cnt[MAXN * RELS];
__device__ int    g_deg[MAXN];
__device__ int    g_offs[MAXN + 1];
__device__ int    g_cur[MAXN];
__device__ unsigned g_csr[MAXE];

__device__ __half g_xh[(size_t)MAXN * 256];
__device__ __half g_xl[(size_t)MAXN * 256];
__device__ __half g_hh[(size_t)MAXN * 256];
__device__ __half g_hl[(size_t)MAXN * 256];

__device__ __half g_w1[2304 * 256];            // pre-transposed fp16
__device__ __half g_w2[1152 * 256];

// ---------------------------------------------------------------------------
__device__ __forceinline__ void ldsm4(uint32_t* r, uint32_t addr)
{
    asm volatile("ldmatrix.sync.aligned.m8n8.x4.shared.b16 {%0,%1,%2,%3}, [%4];"
                 : "=r"(r[0]), "=r"(r[1]), "=r"(r[2]), "=r"(r[3]) : "r"(addr));
}

__device__ __forceinline__ void mma_f16(float* c, const uint32_t* a, const uint32_t* b)
{
    asm volatile(
        "mma.sync.aligned.m16n8k16.row.col.f32.f16.f16.f32 "
        "{%0,%1,%2,%3}, {%4,%5,%6,%7}, {%8,%9}, {%0,%1,%2,%3};"
        : "+f"(c[0]), "+f"(c[1]), "+f"(c[2]), "+f"(c[3])
        : "r"(a[0]), "r"(a[1]), "r"(a[2]), "r"(a[3]), "r"(b[0]), "r"(b[1]));
}

#define CP_COMMIT() asm volatile("cp.async.commit_group;" ::: "memory")
#define CP_WAIT1()  asm volatile("cp.async.wait_group 1;" ::: "memory")
#define CP_WAIT0()  asm volatile("cp.async.wait_group 0;" ::: "memory")

__device__ __forceinline__ void cp16(uint32_t dst, const void* src, int sz)
{
    asm volatile("cp.async.ca.shared.global [%0], [%1], 16, %2;"
                 :: "r"(dst), "l"(src), "r"(sz));
}

// ---------------------------------------------------------------------------
// Pipelined GEMM: C[M,T] = (Ah+Al)[M,256] @ W[T,256]^T, fp16 out.
// CTA 128x128, 8 warps (2x4 of 64x32), kc=32, 2-stage cp.async, 2 syncs/iter.
// smem/stage: 3 operands x 128 rows x 80B = 30720 B. Total 60 KB.
// ---------------------------------------------------------------------------
#define OP_BYTES 10240
#define STG_BYTES 30720
#define SMEMP (2 * STG_BYTES)

__global__ void __launch_bounds__(256)
gemm_pipe(const __half* __restrict__ Ah, const __half* __restrict__ Al,
          int M,
          const __half* __restrict__ Bw,
          __half* __restrict__ C, int ldc)
{
    extern __shared__ char smem[];
    uint32_t sb0;
    asm("{ .reg .u64 t; cvta.to.shared.u64 t, %1; cvt.u32.u64 %0, t; }"
        : "=r"(sb0) : "l"(smem));

    const int tid  = threadIdx.x;
    const int wid  = tid >> 5;
    const int lane = tid & 31;
    const int wm   = wid >> 2;
    const int wn   = wid & 3;
    const int bm   = blockIdx.x * 128;
    const int bn   = blockIdx.y * 128;

    float acc[4][4][4];
#pragma unroll
    for (int i = 0; i < 4; i++)
#pragma unroll
        for (int j = 0; j < 4; j++)
#pragma unroll
            for (int q = 0; q < 4; q++) acc[i][j][q] = 0.f;

    const int q8 = lane >> 3;
    const int lg = lane & 7;

    // stage loader: 3 x 512 16B-chunks, 6 per thread
    auto load_stage = [&](int stage, int k0) {
        uint32_t sb = sb0 + stage * STG_BYTES;
#pragma unroll
        for (int i = 0; i < 6; i++) {
            int op  = i >> 1;
            int idx = (i & 1) * 256 + tid;
            int row = idx >> 2;
            int seg = (idx & 3) * 8;
            const __half* g;
            int grow;
            int sz = 16;
            if (op == 0)      { g = Ah; grow = bm + row; if (grow >= M) { grow = 0; sz = 0; } }
            else if (op == 1) { g = Al; grow = bm + row; if (grow >= M) { grow = 0; sz = 0; } }
            else              { g = Bw; grow = bn + row; }
            cp16(sb + op * OP_BYTES + row * 80 + seg * 2,
                 g + (size_t)grow * 256 + k0 + seg, sz);
        }
        CP_COMMIT();
    };

    load_stage(0, 0);

    for (int kb = 0; kb < 8; kb++) {
        if (kb < 7) load_stage((kb + 1) & 1, (kb + 1) * 32);
        if (kb < 7) CP_WAIT1(); else CP_WAIT0();
        __syncthreads();

        const uint32_t sb = sb0 + (kb & 1) * STG_BYTES;
        const uint32_t sAh_b = sb;
        const uint32_t sAl_b = sb + OP_BYTES;
        const uint32_t sBw_b = sb + 2 * OP_BYTES;

#pragma unroll
        for (int ks = 0; ks < 2; ks++) {
            uint32_t bw[8];
#pragma unroll
            for (int np = 0; np < 2; np++) {
                int nrow = wn * 32 + np * 16 + lg + ((q8 >> 1) ? 8 : 0);
                int bcol = ks * 32 + ((q8 & 1) ? 16 : 0);
                ldsm4(&bw[np * 4], sBw_b + nrow * 80 + bcol);
            }
#pragma unroll
            for (int mt = 0; mt < 4; mt++) {
                int arow = wm * 64 + mt * 16 + lg + ((q8 & 1) ? 8 : 0);
                int acol = ks * 32 + ((q8 >> 1) ? 16 : 0);
                uint32_t ah[4], al[4];
                ldsm4(ah, sAh_b + arow * 80 + acol);
                ldsm4(al, sAl_b + arow * 80 + acol);
#pragma unroll
                for (int nt = 0; nt < 4; nt++) mma_f16(acc[mt][nt], ah, &bw[nt * 2]);
#pragma unroll
                for (int nt = 0; nt < 4; nt++) mma_f16(acc[mt][nt], al, &bw[nt * 2]);
            }
        }
        __syncthreads();
    }

    // ---- epilogue (fp16) ----
#pragma unroll
    for (int mt = 0; mt < 4; mt++) {
#pragma unroll
        for (int nt = 0; nt < 4; nt++) {
            int gr0  = bm + wm * 64 + mt * 16 + (lane >> 2);
            int gcol = bn + wn * 32 + nt * 8 + (lane & 3) * 2;
#pragma unroll
            for (int h = 0; h < 2; h++) {
                int gr = gr0 + h * 8;
                if (gr < M) {
                    *(__half2*)(C + (size_t)gr * ldc + gcol) =
                        __floats2half2_rn(acc[mt][nt][h * 2 + 0], acc[mt][nt][h * 2 + 1]);
                }
            }
        }
    }
}

// ---------------------------------------------------------------------------
// Prep kernels
// ---------------------------------------------------------------------------
__global__ void convw_kernel(const float* __restrict__ W,
                             __half* __restrict__ w, int N, int total)
{
    int idx = blockIdx.x * blockDim.x + threadIdx.x;
    if (idx >= total) return;
    int n = idx % N;
    int k = (idx / N) & 255;
    int r = idx / (N * 256);
    w[((size_t)r * N + n) * 256 + k] = __float2half_rn(W[idx]);
}

__global__ void split_kernel(const float* __restrict__ X,
                             __half* __restrict__ hi,
                             __half* __restrict__ lo,
                             size_t total)
{
    size_t i = (size_t)blockIdx.x * blockDim.x + threadIdx.x;
    if (i >= total) return;
    float f = X[i];
    __half h = __float2half_rn(f);
    hi[i] = h;
    lo[i] = __float2half_rn(f - __half2float(h));
}

// ---------------------------------------------------------------------------
// CSR construction
// ---------------------------------------------------------------------------
__global__ void zero_int_kernel(int* p, int n)
{
    int i = blockIdx.x * blockDim.x + threadIdx.x;
    if (i < n) p[i] = 0;
}

__global__ void count_kernel(const int* __restrict__ ei,
                             const int* __restrict__ et,
                             int* __restrict__ cnt, int E)
{
    int e = blockIdx.x * blockDim.x + threadIdx.x;
    if (e < E) atomicAdd(&cnt[ei[E + e] * RELS + et[e]], 1);
}

__global__ void deg_kernel(const int* __restrict__ cnt, int* __restrict__ deg, int n)
{
    int i = blockIdx.x * blockDim.x + threadIdx.x;
    if (i < n) {
        int s = 0;
#pragma unroll
        for (int r = 0; r < RELS; r++) s += cnt[i * RELS + r];
        deg[i] = s;
    }
}

__global__ void scan_kernel(const int* __restrict__ deg, int* __restrict__ offs, int n)
{
    __shared__ int buf[1024];
    __shared__ int carry;
    const int tid = threadIdx.x;
    if (tid == 0) carry = 0;
    __syncthreads();
    for (int base = 0; base < n; base += 1024) {
        int i = base + tid;
        int v = (i < n) ? deg[i] : 0;
        buf[tid] = v;
        __syncthreads();
        for (int d = 1; d < 1024; d <<= 1) {
            int t = (tid >= d) ? buf[tid - d] : 0;
            __syncthreads();
            buf[tid] += t;
            __syncthreads();
        }
        if (i < n) offs[i] = carry + buf[tid] - v;
        __syncthreads();
        if (tid == 0) carry += buf[1023];
        __syncthreads();
    }
    if (tid == 0) offs[n] = carry;
}

__global__ void fill_kernel(const int* __restrict__ ei,
                            const int* __restrict__ et,
                            const int* __restrict__ offs,
                            int* __restrict__ cur,
                            unsigned* __restrict__ csr, int E)
{
    int e = blockIdx.x * blockDim.x + threadIdx.x;
    if (e < E) {
        int d = ei[E + e];
        int pos = offs[d] + atomicAdd(&cur[d], 1);
        csr[pos] = (unsigned)ei[e] | ((unsigned)et[e] << 16);
    }
}

// ---------------------------------------------------------------------------
// Gather. Layer 1: root(from Y1ext)+bias+messages, relu, fp16 hi/lo split.
// ---------------------------------------------------------------------------
__global__ void __launch_bounds__(128)
gather1_kernel(const __half* __restrict__ Y,
               const unsigned* __restrict__ csr,
               const int* __restrict__ offs,
               const int* __restrict__ cnt,
               const float* __restrict__ bias,
               __half* __restrict__ hh,
               __half* __restrict__ hl)
{
    const int dst = blockIdx.x;
    const int tid = threadIdx.x;
    __shared__ float nrm[8];
    if (tid < 8) nrm[tid] = 1.0f / (float)max(cnt[dst * RELS + tid], 1);
    const int s = offs[dst], t = offs[dst + 1];
    __syncthreads();

    float2 bb = *(const float2*)(bias + tid * 2);
    float2 rt = __half22float2(__ldg((const __half2*)(Y + (size_t)dst * 2304 + 2048) + tid));
    float2 acc = make_float2(rt.x + bb.x, rt.y + bb.y);

    int e = s;
    for (; e + 4 <= t; e += 4) {
        unsigned p0 = csr[e], p1 = csr[e + 1], p2 = csr[e + 2], p3 = csr[e + 3];
        __half2 y0 = __ldg((const __half2*)(Y + (size_t)(p0 & 0xFFFFu) * 2304 + (p0 >> 16) * 256) + tid);
        __half2 y1 = __ldg((const __half2*)(Y + (size_t)(p1 & 0xFFFFu) * 2304 + (p1 >> 16) * 256) + tid);
        __half2 y2 = __ldg((const __half2*)(Y + (size_t)(p2 & 0xFFFFu) * 2304 + (p2 >> 16) * 256) + tid);
        __half2 y3 = __ldg((const __half2*)(Y + (size_t)(p3 & 0xFFFFu) * 2304 + (p3 >> 16) * 256) + tid);
        float2 f0 = __half22float2(y0), f1 = __half22float2(y1);
        float2 f2 = __half22float2(y2), f3 = __half22float2(y3);
        float n0 = nrm[p0 >> 16], n1 = nrm[p1 >> 16], n2 = nrm[p2 >> 16], n3 = nrm[p3 >> 16];
        acc.x += f0.x * n0 + f1.x * n1 + f2.x * n2 + f3.x * n3;
        acc.y += f0.y * n0 + f1.y * n1 + f2.y * n2 + f3.y * n3;
    }
    for (; e < t; e++) {
        unsigned p = csr[e];
        __half2 y = __ldg((const __half2*)(Y + (size_t)(p & 0xFFFFu) * 2304 + (p >> 16) * 256) + tid);
        float2 f = __half22float2(y);
        float n = nrm[p >> 16];
        acc.x += f.x * n;
        acc.y += f.y * n;
    }

    acc.x = fmaxf(acc.x, 0.f);
    acc.y = fmaxf(acc.y, 0.f);
    __half h0 = __float2half_rn(acc.x);
    __half h1 = __float2half_rn(acc.y);
    __half l0 = __float2half_rn(acc.x - __half2float(h0));
    __half l1 = __float2half_rn(acc.y - __half2float(h1));
    *(__half2*)(hh + (size_t)dst * 256 + tid * 2) = __halves2half2(h0, h1);
    *(__half2*)(hl + (size_t)dst * 256 + tid * 2) = __halves2half2(l0, l1);
}

// Layer 2: out = root(from Y2ext) + bias + messages. 64 thr.
__global__ void __launch_bounds__(64)
gather2_kernel(const __half* __restrict__ Y,
               const unsigned* __restrict__ csr,
               const int* __restrict__ offs,
               const int* __restrict__ cnt,
               const float* __restrict__ bias,
               float* __restrict__ out)
{
    const int dst = blockIdx.x;
    const int tid = threadIdx.x;
    __shared__ float nrm[8];
    if (tid < 8) nrm[tid] = 1.0f / (float)max(cnt[dst * RELS + tid], 1);
    const int s = offs[dst], t = offs[dst + 1];
    __syncthreads();

    float2 bb = *(const float2*)(bias + tid * 2);
    float2 rt = __half22float2(__ldg((const __half2*)(Y + (size_t)dst * 1152 + 1024) + tid));
    float2 acc = make_float2(rt.x + bb.x, rt.y + bb.y);

    int e = s;
    for (; e + 4 <= t; e += 4) {
        unsigned p0 = csr[e], p1 = csr[e + 1], p2 = csr[e + 2], p3 = csr[e + 3];
        __half2 y0 = __ldg((const __half2*)(Y + (size_t)(p0 & 0xFFFFu) * 1152 + (p0 >> 16) * 128) + tid);
        __half2 y1 = __ldg((const __half2*)(Y + (size_t)(p1 & 0xFFFFu) * 1152 + (p1 >> 16) * 128) + tid);
        __half2 y2 = __ldg((const __half2*)(Y + (size_t)(p2 & 0xFFFFu) * 1152 + (p2 >> 16) * 128) + tid);
        __half2 y3 = __ldg((const __half2*)(Y + (size_t)(p3 & 0xFFFFu) * 1152 + (p3 >> 16) * 128) + tid);
        float2 f0 = __half22float2(y0), f1 = __half22float2(y1);
        float2 f2 = __half22float2(y2), f3 = __half22float2(y3);
        float n0 = nrm[p0 >> 16], n1 = nrm[p1 >> 16], n2 = nrm[p2 >> 16], n3 = nrm[p3 >> 16];
        acc.x += f0.x * n0 + f1.x * n1 + f2.x * n2 + f3.x * n3;
        acc.y += f0.y * n0 + f1.y * n1 + f2.y * n2 + f3.y * n3;
    }
    for (; e < t; e++) {
        unsigned p = csr[e];
        __half2 y = __ldg((const __half2*)(Y + (size_t)(p & 0xFFFFu) * 1152 + (p >> 16) * 128) + tid);
        float2 f = __half22float2(y);
        float n = nrm[p >> 16];
        acc.x += f.x * n;
        acc.y += f.y * n;
    }
    *(float2*)(out + (size_t)dst * 128 + tid * 2) = acc;
}

// ---------------------------------------------------------------------------
extern "C" void kernel_launch(void* const* d_in, const int* in_sizes, int n_in,
                              void* d_out, int out_size)
{
    const float* x     = (const float*)d_in[0];
    const int*   ei    = (const int*)d_in[1];
    const int*   et    = (const int*)d_in[2];
    const float* W1    = (const float*)d_in[3];
    const float* root1 = (const float*)d_in[4];
    const float* b1    = (const float*)d_in[5];
    const float* W2    = (const float*)d_in[6];
    const float* root2 = (const float*)d_in[7];
    const float* b2    = (const float*)d_in[8];
    float*       out   = (float*)d_out;

    const int N = in_sizes[0] / 256;
    const int E = in_sizes[2];

    __half *Y1, *Y2, *xh, *xl, *hh, *hl, *w1, *w2;
    int *cnt, *deg, *offs, *cur;
    unsigned* csr;
    cudaGetSymbolAddress((void**)&Y1, g_Y1);
    cudaGetSymbolAddress((void**)&Y2, g_Y2);
    cudaGetSymbolAddress((void**)&cnt, g_cnt);
    cudaGetSymbolAddress((void**)&deg, g_deg);
    cudaGetSymbolAddress((void**)&offs, g_offs);
    cudaGetSymbolAddress((void**)&cur, g_cur);
    cudaGetSymbolAddress((void**)&csr, g_csr);
    cudaGetSymbolAddress((void**)&xh, g_xh);
    cudaGetSymbolAddress((void**)&xl, g_xl);
    cudaGetSymbolAddress((void**)&hh, g_hh);
    cudaGetSymbolAddress((void**)&hl, g_hl);
    cudaGetSymbolAddress((void**)&w1, g_w1);
    cudaGetSymbolAddress((void**)&w2, g_w2);

    static cudaStream_t sCsr = nullptr;
    static cudaEvent_t evFork = nullptr, evCsrDone = nullptr;
    static int attr_set = 0;
    if (!attr_set) {
        cudaFuncSetAttribute(gemm_pipe, cudaFuncAttributeMaxDynamicSharedMemorySize, SMEMP);
        cudaStreamCreateWithFlags(&sCsr, cudaStreamNonBlocking);
        cudaEventCreateWithFlags(&evFork, cudaEventDisableTiming);
        cudaEventCreateWithFlags(&evCsrDone, cudaEventDisableTiming);
        attr_set = 1;
    }

    // ---- fork: CSR build + layer-2 weight prep on side stream ----
    cudaEventRecord(evFork, 0);
    cudaStreamWaitEvent(sCsr, evFork, 0);

    zero_int_kernel<<<(N * RELS + 255) / 256, 256, 0, sCsr>>>(cnt, N * RELS);
    zero_int_kernel<<<(N + 255) / 256, 256, 0, sCsr>>>(cur, N);
    count_kernel<<<(E + 255) / 256, 256, 0, sCsr>>>(ei, et, cnt, E);
    deg_kernel<<<(N + 255) / 256, 256, 0, sCsr>>>(cnt, deg, N);
    scan_kernel<<<1, 1024, 0, sCsr>>>(deg, offs, N);
    fill_kernel<<<(E + 255) / 256, 256, 0, sCsr>>>(ei, et, offs, cur, csr, E);
    convw_kernel<<<(8 * 256 * 128 + 255) / 256, 256, 0, sCsr>>>(W2, w2, 128, 8 * 256 * 128);
    convw_kernel<<<(256 * 128 + 255) / 256, 256, 0, sCsr>>>(root2, w2 + 1024 * 256, 128, 256 * 128);
    cudaEventRecord(evCsrDone, sCsr);

    // main stream: layer-1 weight + input prep
    convw_kernel<<<(8 * 256 * 256 + 255) / 256, 256>>>(W1, w1, 256, 8 * 256 * 256);
    convw_kernel<<<(256 * 256 + 255) / 256, 256>>>(root1, w1 + 2048 * 256, 256, 256 * 256);
    split_kernel<<<(int)(((size_t)N * 256 + 255) / 256), 256>>>(x, xh, xl, (size_t)N * 256);

    const int mtiles = (N + 127) / 128;

    // ---- layer 1: 18 n-tiles (8 rel x 2 + root x 2) ----
    gemm_pipe<<<dim3(mtiles, 18), 256, SMEMP>>>(xh, xl, N, w1, Y1, 2304);

    // join: gather1 needs the CSR (and GEMM2 the W2 prep, covered by same event)
    cudaStreamWaitEvent(0, evCsrDone, 0);
    gather1_kernel<<<N, 128>>>(Y1, csr, offs, cnt, b1, hh, hl);

    // ---- layer 2: 9 n-tiles (8 rel + root) ----
    gemm_pipe<<<dim3(mtiles, 9), 256, SMEMP>>>(hh, hl, N, w2, Y2, 1152);
    gather2_kernel<<<N, 64>>>(Y2, csr, offs, cnt, b2, out);
}

// round 12
// speedup vs baseline: 1.4916x; 1.0299x over previous
#include <cuda_runtime.h>
#include <cuda_bf16.h>
#include <cuda_fp16.h>
#include <cstdint>

// ============================================================================
// RGCN 2-layer, transform-first. Root GEMM fused as a 9th relation.
// GEMMs: mma.sync fp16, x split hi+lo (2 MMA passes), W rounded to fp16 once.
// Warp grid 4x2 (32x64 warp tiles) => LDSM traffic matches HMMA floor.
// 2-stage cp.async pipeline. Messages+root fp16. CSR pull aggregation,
// CSR build + W2 prep forked onto a side stream.
// ============================================================================

#define MAXN 50000
#define MAXE 840000
#define RELS 8

__device__ __half g_Y1[(size_t)MAXN * 2304];   // [N, 8*256 + 256(root)]
__device__ __half g_Y2[(size_t)MAXN * 1152];   // [N, 8*128 + 128(root)]
__device__ int    g_cnt[MAXN * RELS];
__device__ int    g_deg[MAXN];
__device__ int    g_offs[MAXN + 1];
__device__ int    g_cur[MAXN];
__device__ unsigned g_csr[MAXE];

__device__ __half g_xh[(size_t)MAXN * 256];
__device__ __half g_xl[(size_t)MAXN * 256];
__device__ __half g_hh[(size_t)MAXN * 256];
__device__ __half g_hl[(size_t)MAXN * 256];

__device__ __half g_w1[2304 * 256];            // pre-transposed fp16
__device__ __half g_w2[1152 * 256];

// ---------------------------------------------------------------------------
__device__ __forceinline__ void ldsm4(uint32_t* r, uint32_t addr)
{
    asm volatile("ldmatrix.sync.aligned.m8n8.x4.shared.b16 {%0,%1,%2,%3}, [%4];"
                 : "=r"(r[0]), "=r"(r[1]), "=r"(r[2]), "=r"(r[3]) : "r"(addr));
}

__device__ __forceinline__ void mma_f16(float* c, const uint32_t* a, const uint32_t* b)
{
    asm volatile(
        "mma.sync.aligned.m16n8k16.row.col.f32.f16.f16.f32 "
        "{%0,%1,%2,%3}, {%4,%5,%6,%7}, {%8,%9}, {%0,%1,%2,%3};"
        : "+f"(c[0]), "+f"(c[1]), "+f"(c[2]), "+f"(c[3])
        : "r"(a[0]), "r"(a[1]), "r"(a[2]), "r"(a[3]), "r"(b[0]), "r"(b[1]));
}

#define CP_COMMIT() asm volatile("cp.async.commit_group;" ::: "memory")
#define CP_WAIT1()  asm volatile("cp.async.wait_group 1;" ::: "memory")
#define CP_WAIT0()  asm volatile("cp.async.wait_group 0;" ::: "memory")

__device__ __forceinline__ void cp16(uint32_t dst, const void* src, int sz)
{
    asm volatile("cp.async.ca.shared.global [%0], [%1], 16, %2;"
                 :: "r"(dst), "l"(src), "r"(sz));
}

// ---------------------------------------------------------------------------
// Pipelined GEMM: C[M,T] = (Ah+Al)[M,256] @ W[T,256]^T, fp16 out.
// CTA 128x128, 8 warps (4x2 of 32x64), kc=32, 2-stage cp.async, 2 syncs/iter.
// smem/stage: 3 operands x 128 rows x 80B = 30720 B. Total 60 KB.
// ---------------------------------------------------------------------------
#define OP_BYTES 10240
#define STG_BYTES 30720
#define SMEMP (2 * STG_BYTES)

__global__ void __launch_bounds__(256)
gemm_pipe(const __half* __restrict__ Ah, const __half* __restrict__ Al,
          int M,
          const __half* __restrict__ Bw,
          __half* __restrict__ C, int ldc)
{
    extern __shared__ char smem[];
    uint32_t sb0;
    asm("{ .reg .u64 t; cvta.to.shared.u64 t, %1; cvt.u32.u64 %0, t; }"
        : "=r"(sb0) : "l"(smem));

    const int tid  = threadIdx.x;
    const int wid  = tid >> 5;
    const int lane = tid & 31;
    const int wm   = wid >> 1;      // 0..3
    const int wn   = wid & 1;       // 0..1
    const int bm   = blockIdx.x * 128;
    const int bn   = blockIdx.y * 128;

    float acc[2][8][4];
#pragma unroll
    for (int i = 0; i < 2; i++)
#pragma unroll
        for (int j = 0; j < 8; j++)
#pragma unroll
            for (int q = 0; q < 4; q++) acc[i][j][q] = 0.f;

    const int q8 = lane >> 3;
    const int lg = lane & 7;

    // stage loader: 3 x 512 16B-chunks, 6 per thread
    auto load_stage = [&](int stage, int k0) {
        uint32_t sb = sb0 + stage * STG_BYTES;
#pragma unroll
        for (int i = 0; i < 6; i++) {
            int op  = i >> 1;
            int idx = (i & 1) * 256 + tid;
            int row = idx >> 2;
            int seg = (idx & 3) * 8;
            const __half* g;
            int grow;
            int sz = 16;
            if (op == 0)      { g = Ah; grow = bm + row; if (grow >= M) { grow = 0; sz = 0; } }
            else if (op == 1) { g = Al; grow = bm + row; if (grow >= M) { grow = 0; sz = 0; } }
            else              { g = Bw; grow = bn + row; }
            cp16(sb + op * OP_BYTES + row * 80 + seg * 2,
                 g + (size_t)grow * 256 + k0 + seg, sz);
        }
        CP_COMMIT();
    };

    load_stage(0, 0);

    for (int kb = 0; kb < 8; kb++) {
        if (kb < 7) load_stage((kb + 1) & 1, (kb + 1) * 32);
        if (kb < 7) CP_WAIT1(); else CP_WAIT0();
        __syncthreads();

        const uint32_t sb = sb0 + (kb & 1) * STG_BYTES;
        const uint32_t sAh_b = sb;
        const uint32_t sAl_b = sb + OP_BYTES;
        const uint32_t sBw_b = sb + 2 * OP_BYTES;

#pragma unroll
        for (int ks = 0; ks < 2; ks++) {
            uint32_t bw[16];
#pragma unroll
            for (int np = 0; np < 4; np++) {
                int nrow = wn * 64 + np * 16 + lg + ((q8 >> 1) ? 8 : 0);
                int bcol = ks * 32 + ((q8 & 1) ? 16 : 0);
                ldsm4(&bw[np * 4], sBw_b + nrow * 80 + bcol);
            }
#pragma unroll
            for (int mt = 0; mt < 2; mt++) {
                int arow = wm * 32 + mt * 16 + lg + ((q8 & 1) ? 8 : 0);
                int acol = ks * 32 + ((q8 >> 1) ? 16 : 0);
                uint32_t ah[4], al[4];
                ldsm4(ah, sAh_b + arow * 80 + acol);
                ldsm4(al, sAl_b + arow * 80 + acol);
#pragma unroll
                for (int nt = 0; nt < 8; nt++) mma_f16(acc[mt][nt], ah, &bw[nt * 2]);
#pragma unroll
                for (int nt = 0; nt < 8; nt++) mma_f16(acc[mt][nt], al, &bw[nt * 2]);
            }
        }
        __syncthreads();
    }

    // ---- epilogue (fp16) ----
#pragma unroll
    for (int mt = 0; mt < 2; mt++) {
#pragma unroll
        for (int nt = 0; nt < 8; nt++) {
            int gr0  = bm + wm * 32 + mt * 16 + (lane >> 2);
            int gcol = bn + wn * 64 + nt * 8 + (lane & 3) * 2;
#pragma unroll
            for (int h = 0; h < 2; h++) {
                int gr = gr0 + h * 8;
                if (gr < M) {
                    *(__half2*)(C + (size_t)gr * ldc + gcol) =
                        __floats2half2_rn(acc[mt][nt][h * 2 + 0], acc[mt][nt][h * 2 + 1]);
                }
            }
        }
    }
}

// ---------------------------------------------------------------------------
// Prep kernels
// ---------------------------------------------------------------------------
__global__ void convw_kernel(const float* __restrict__ W,
                             __half* __restrict__ w, int N, int total)
{
    int idx = blockIdx.x * blockDim.x + threadIdx.x;
    if (idx >= total) return;
    int n = idx % N;
    int k = (idx / N) & 255;
    int r = idx / (N * 256);
    w[((size_t)r * N + n) * 256 + k] = __float2half_rn(W[idx]);
}

__global__ void split_kernel(const float* __restrict__ X,
                             __half* __restrict__ hi,
                             __half* __restrict__ lo,
                             size_t total)
{
    size_t i = (size_t)blockIdx.x * blockDim.x + threadIdx.x;
    if (i >= total) return;
    float f = X[i];
    __half h = __float2half_rn(f);
    hi[i] = h;
    lo[i] = __float2half_rn(f - __half2float(h));
}

// ---------------------------------------------------------------------------
// CSR construction
// ---------------------------------------------------------------------------
__global__ void zero_int_kernel(int* p, int n)
{
    int i = blockIdx.x * blockDim.x + threadIdx.x;
    if (i < n) p[i] = 0;
}

__global__ void count_kernel(const int* __restrict__ ei,
                             const int* __restrict__ et,
                             int* __restrict__ cnt, int E)
{
    int e = blockIdx.x * blockDim.x + threadIdx.x;
    if (e < E) atomicAdd(&cnt[ei[E + e] * RELS + et[e]], 1);
}

__global__ void deg_kernel(const int* __restrict__ cnt, int* __restrict__ deg, int n)
{
    int i = blockIdx.x * blockDim.x + threadIdx.x;
    if (i < n) {
        int s = 0;
#pragma unroll
        for (int r = 0; r < RELS; r++) s += cnt[i * RELS + r];
        deg[i] = s;
    }
}

__global__ void scan_kernel(const int* __restrict__ deg, int* __restrict__ offs, int n)
{
    __shared__ int buf[1024];
    __shared__ int carry;
    const int tid = threadIdx.x;
    if (tid == 0) carry = 0;
    __syncthreads();
    for (int base = 0; base < n; base += 1024) {
        int i = base + tid;
        int v = (i < n) ? deg[i] : 0;
        buf[tid] = v;
        __syncthreads();
        for (int d = 1; d < 1024; d <<= 1) {
            int t = (tid >= d) ? buf[tid - d] : 0;
            __syncthreads();
            buf[tid] += t;
            __syncthreads();
        }
        if (i < n) offs[i] = carry + buf[tid] - v;
        __syncthreads();
        if (tid == 0) carry += buf[1023];
        __syncthreads();
    }
    if (tid == 0) offs[n] = carry;
}

__global__ void fill_kernel(const int* __restrict__ ei,
                            const int* __restrict__ et,
                            const int* __restrict__ offs,
                            int* __restrict__ cur,
                            unsigned* __restrict__ csr, int E)
{
    int e = blockIdx.x * blockDim.x + threadIdx.x;
    if (e < E) {
        int d = ei[E + e];
        int pos = offs[d] + atomicAdd(&cur[d], 1);
        csr[pos] = (unsigned)ei[e] | ((unsigned)et[e] << 16);
    }
}

// ---------------------------------------------------------------------------
// Gather. Layer 1: root(from Y1ext)+bias+messages, relu, fp16 hi/lo split.
// ---------------------------------------------------------------------------
__global__ void __launch_bounds__(128)
gather1_kernel(const __half* __restrict__ Y,
               const unsigned* __restrict__ csr,
               const int* __restrict__ offs,
               const int* __restrict__ cnt,
               const float* __restrict__ bias,
               __half* __restrict__ hh,
               __half* __restrict__ hl)
{
    const int dst = blockIdx.x;
    const int tid = threadIdx.x;
    __shared__ float nrm[8];
    if (tid < 8) nrm[tid] = 1.0f / (float)max(cnt[dst * RELS + tid], 1);
    const int s = offs[dst], t = offs[dst + 1];
    __syncthreads();

    float2 bb = *(const float2*)(bias + tid * 2);
    float2 rt = __half22float2(__ldg((const __half2*)(Y + (size_t)dst * 2304 + 2048) + tid));
    float2 acc = make_float2(rt.x + bb.x, rt.y + bb.y);

    int e = s;
    for (; e + 4 <= t; e += 4) {
        unsigned p0 = csr[e], p1 = csr[e + 1], p2 = csr[e + 2], p3 = csr[e + 3];
        __half2 y0 = __ldg((const __half2*)(Y + (size_t)(p0 & 0xFFFFu) * 2304 + (p0 >> 16) * 256) + tid);
        __half2 y1 = __ldg((const __half2*)(Y + (size_t)(p1 & 0xFFFFu) * 2304 + (p1 >> 16) * 256) + tid);
        __half2 y2 = __ldg((const __half2*)(Y + (size_t)(p2 & 0xFFFFu) * 2304 + (p2 >> 16) * 256) + tid);
        __half2 y3 = __ldg((const __half2*)(Y + (size_t)(p3 & 0xFFFFu) * 2304 + (p3 >> 16) * 256) + tid);
        float2 f0 = __half22float2(y0), f1 = __half22float2(y1);
        float2 f2 = __half22float2(y2), f3 = __half22float2(y3);
        float n0 = nrm[p0 >> 16], n1 = nrm[p1 >> 16], n2 = nrm[p2 >> 16], n3 = nrm[p3 >> 16];
        acc.x += f0.x * n0 + f1.x * n1 + f2.x * n2 + f3.x * n3;
        acc.y += f0.y * n0 + f1.y * n1 + f2.y * n2 + f3.y * n3;
    }
    for (; e < t; e++) {
        unsigned p = csr[e];
        __half2 y = __ldg((const __half2*)(Y + (size_t)(p & 0xFFFFu) * 2304 + (p >> 16) * 256) + tid);
        float2 f = __half22float2(y);
        float n = nrm[p >> 16];
        acc.x += f.x * n;
        acc.y += f.y * n;
    }

    acc.x = fmaxf(acc.x, 0.f);
    acc.y = fmaxf(acc.y, 0.f);
    __half h0 = __float2half_rn(acc.x);
    __half h1 = __float2half_rn(acc.y);
    __half l0 = __float2half_rn(acc.x - __half2float(h0));
    __half l1 = __float2half_rn(acc.y - __half2float(h1));
    *(__half2*)(hh + (size_t)dst * 256 + tid * 2) = __halves2half2(h0, h1);
    *(__half2*)(hl + (size_t)dst * 256 + tid * 2) = __halves2half2(l0, l1);
}

// Layer 2: out = root(from Y2ext) + bias + messages. 64 thr.
__global__ void __launch_bounds__(64)
gather2_kernel(const __half* __restrict__ Y,
               const unsigned* __restrict__ csr,
               const int* __restrict__ offs,
               const int* __restrict__ cnt,
               const float* __restrict__ bias,
               float* __restrict__ out)
{
    const int dst = blockIdx.x;
    const int tid = threadIdx.x;
    __shared__ float nrm[8];
    if (tid < 8) nrm[tid] = 1.0f / (float)max(cnt[dst * RELS + tid], 1);
    const int s = offs[dst], t = offs[dst + 1];
    __syncthreads();

    float2 bb = *(const float2*)(bias + tid * 2);
    float2 rt = __half22float2(__ldg((const __half2*)(Y + (size_t)dst * 1152 + 1024) + tid));
    float2 acc = make_float2(rt.x + bb.x, rt.y + bb.y);

    int e = s;
    for (; e + 4 <= t; e += 4) {
        unsigned p0 = csr[e], p1 = csr[e + 1], p2 = csr[e + 2], p3 = csr[e + 3];
        __half2 y0 = __ldg((const __half2*)(Y + (size_t)(p0 & 0xFFFFu) * 1152 + (p0 >> 16) * 128) + tid);
        __half2 y1 = __ldg((const __half2*)(Y + (size_t)(p1 & 0xFFFFu) * 1152 + (p1 >> 16) * 128) + tid);
        __half2 y2 = __ldg((const __half2*)(Y + (size_t)(p2 & 0xFFFFu) * 1152 + (p2 >> 16) * 128) + tid);
        __half2 y3 = __ldg((const __half2*)(Y + (size_t)(p3 & 0xFFFFu) * 1152 + (p3 >> 16) * 128) + tid);
        float2 f0 = __half22float2(y0), f1 = __half22float2(y1);
        float2 f2 = __half22float2(y2), f3 = __half22float2(y3);
        float n0 = nrm[p0 >> 16], n1 = nrm[p1 >> 16], n2 = nrm[p2 >> 16], n3 = nrm[p3 >> 16];
        acc.x += f0.x * n0 + f1.x * n1 + f2.x * n2 + f3.x * n3;
        acc.y += f0.y * n0 + f1.y * n1 + f2.y * n2 + f3.y * n3;
    }
    for (; e < t; e++) {
        unsigned p = csr[e];
        __half2 y = __ldg((const __half2*)(Y + (size_t)(p & 0xFFFFu) * 1152 + (p >> 16) * 128) + tid);
        float2 f = __half22float2(y);
        float n = nrm[p >> 16];
        acc.x += f.x * n;
        acc.y += f.y * n;
    }
    *(float2*)(out + (size_t)dst * 128 + tid * 2) = acc;
}

// ---------------------------------------------------------------------------
extern "C" void kernel_launch(void* const* d_in, const int* in_sizes, int n_in,
                              void* d_out, int out_size)
{
    const float* x     = (const float*)d_in[0];
    const int*   ei    = (const int*)d_in[1];
    const int*   et    = (const int*)d_in[2];
    const float* W1    = (const float*)d_in[3];
    const float* root1 = (const float*)d_in[4];
    const float* b1    = (const float*)d_in[5];
    const float* W2    = (const float*)d_in[6];
    const float* root2 = (const float*)d_in[7];
    const float* b2    = (const float*)d_in[8];
    float*       out   = (float*)d_out;

    const int N = in_sizes[0] / 256;
    const int E = in_sizes[2];

    __half *Y1, *Y2, *xh, *xl, *hh, *hl, *w1, *w2;
    int *cnt, *deg, *offs, *cur;
    unsigned* csr;
    cudaGetSymbolAddress((void**)&Y1, g_Y1);
    cudaGetSymbolAddress((void**)&Y2, g_Y2);
    cudaGetSymbolAddress((void**)&cnt, g_cnt);
    cudaGetSymbolAddress((void**)&deg, g_deg);
    cudaGetSymbolAddress((void**)&offs, g_offs);
    cudaGetSymbolAddress((void**)&cur, g_cur);
    cudaGetSymbolAddress((void**)&csr, g_csr);
    cudaGetSymbolAddress((void**)&xh, g_xh);
    cudaGetSymbolAddress((void**)&xl, g_xl);
    cudaGetSymbolAddress((void**)&hh, g_hh);
    cudaGetSymbolAddress((void**)&hl, g_hl);
    cudaGetSymbolAddress((void**)&w1, g_w1);
    cudaGetSymbolAddress((void**)&w2, g_w2);

    static cudaStream_t sCsr = nullptr;
    static cudaEvent_t evFork = nullptr, evCsrDone = nullptr;
    static int attr_set = 0;
    if (!attr_set) {
        cudaFuncSetAttribute(gemm_pipe, cudaFuncAttributeMaxDynamicSharedMemorySize, SMEMP);
        cudaStreamCreateWithFlags(&sCsr, cudaStreamNonBlocking);
        cudaEventCreateWithFlags(&evFork, cudaEventDisableTiming);
        cudaEventCreateWithFlags(&evCsrDone, cudaEventDisableTiming);
        attr_set = 1;
    }

    // ---- fork: CSR build + layer-2 weight prep on side stream ----
    cudaEventRecord(evFork, 0);
    cudaStreamWaitEvent(sCsr, evFork, 0);

    zero_int_kernel<<<(N * RELS + 255) / 256, 256, 0, sCsr>>>(cnt, N * RELS);
    zero_int_kernel<<<(N + 255) / 256, 256, 0, sCsr>>>(cur, N);
    count_kernel<<<(E + 255) / 256, 256, 0, sCsr>>>(ei, et, cnt, E);
    deg_kernel<<<(N + 255) / 256, 256, 0, sCsr>>>(cnt, deg, N);
    scan_kernel<<<1, 1024, 0, sCsr>>>(deg, offs, N);
    fill_kernel<<<(E + 255) / 256, 256, 0, sCsr>>>(ei, et, offs, cur, csr, E);
    convw_kernel<<<(8 * 256 * 128 + 255) / 256, 256, 0, sCsr>>>(W2, w2, 128, 8 * 256 * 128);
    convw_kernel<<<(256 * 128 + 255) / 256, 256, 0, sCsr>>>(root2, w2 + 1024 * 256, 128, 256 * 128);
    cudaEventRecord(evCsrDone, sCsr);

    // main stream: layer-1 weight + input prep
    convw_kernel<<<(8 * 256 * 256 + 255) / 256, 256>>>(W1, w1, 256, 8 * 256 * 256);
    convw_kernel<<<(256 * 256 + 255) / 256, 256>>>(root1, w1 + 2048 * 256, 256, 256 * 256);
    split_kernel<<<(int)(((size_t)N * 256 + 255) / 256), 256>>>(x, xh, xl, (size_t)N * 256);

    const int mtiles = (N + 127) / 128;

    // ---- layer 1: 18 n-tiles (8 rel x 2 + root x 2) ----
    gemm_pipe<<<dim3(mtiles, 18), 256, SMEMP>>>(xh, xl, N, w1, Y1, 2304);

    // join: gather1 needs the CSR (and GEMM2 the W2 prep, covered by same event)
    cudaStreamWaitEvent(0, evCsrDone, 0);
    gather1_kernel<<<N, 128>>>(Y1, csr, offs, cnt, b1, hh, hl);

    // ---- layer 2: 9 n-tiles (8 rel + root) ----
    gemm_pipe<<<dim3(mtiles, 9), 256, SMEMP>>>(hh, hl, N, w2, Y2, 1152);
    gather2_kernel<<<N, 64>>>(Y2, csr, offs, cnt, b2, out);
}

// round 13
// speedup vs baseline: 1.8556x; 1.2440x over previous
#include <cuda_runtime.h>
#include <cuda_bf16.h>
#include <cuda_fp16.h>
#include <cstdint>

// ============================================================================
// RGCN 2-layer, transform-first. Root GEMM fused as a 9th relation.
// GEMMs: single-pass fp16 mma.sync (x and W each rounded to fp16 once).
// Warp grid 4x2 (32x64 warp tiles). 2-stage cp.async pipeline.
// Messages+root fp16. CSR pull aggregation; CSR build + W2 prep on side stream.
// ============================================================================

#define MAXN 50000
#define MAXE 840000
#define RELS 8

__device__ __half g_Y1[(size_t)MAXN * 2304];   // [N, 8*256 + 256(root)]
__device__ __half g_Y2[(size_t)MAXN * 1152];   // [N, 8*128 + 128(root)]
__device__ int    g_cnt[MAXN * RELS];
__device__ int    g_deg[MAXN];
__device__ int    g_offs[MAXN + 1];
__device__ int    g_cur[MAXN];
__device__ unsigned g_csr[MAXE];

__device__ __half g_x16[(size_t)MAXN * 256];
__device__ __half g_h16[(size_t)MAXN * 256];

__device__ __half g_w1[2304 * 256];            // pre-transposed fp16
__device__ __half g_w2[1152 * 256];

// ---------------------------------------------------------------------------
__device__ __forceinline__ void ldsm4(uint32_t* r, uint32_t addr)
{
    asm volatile("ldmatrix.sync.aligned.m8n8.x4.shared.b16 {%0,%1,%2,%3}, [%4];"
                 : "=r"(r[0]), "=r"(r[1]), "=r"(r[2]), "=r"(r[3]) : "r"(addr));
}

__device__ __forceinline__ void mma_f16(float* c, const uint32_t* a, const uint32_t* b)
{
    asm volatile(
        "mma.sync.aligned.m16n8k16.row.col.f32.f16.f16.f32 "
        "{%0,%1,%2,%3}, {%4,%5,%6,%7}, {%8,%9}, {%0,%1,%2,%3};"
        : "+f"(c[0]), "+f"(c[1]), "+f"(c[2]), "+f"(c[3])
        : "r"(a[0]), "r"(a[1]), "r"(a[2]), "r"(a[3]), "r"(b[0]), "r"(b[1]));
}

#define CP_COMMIT() asm volatile("cp.async.commit_group;" ::: "memory")
#define CP_WAIT1()  asm volatile("cp.async.wait_group 1;" ::: "memory")
#define CP_WAIT0()  asm volatile("cp.async.wait_group 0;" ::: "memory")

__device__ __forceinline__ void cp16(uint32_t dst, const void* src, int sz)
{
    asm volatile("cp.async.ca.shared.global [%0], [%1], 16, %2;"
                 :: "r"(dst), "l"(src), "r"(sz));
}

// ---------------------------------------------------------------------------
// Pipelined GEMM: C[M,T] = A16[M,256] @ W[T,256]^T, fp16 out.
// CTA 128x128, 8 warps (4x2 of 32x64), kc=32, 2-stage cp.async, 2 syncs/iter.
// smem/stage: 2 operands x 128 rows x 80B = 20480 B. Total 40 KB.
// ---------------------------------------------------------------------------
#define OP_BYTES 10240
#define STG_BYTES 20480
#define SMEMP (2 * STG_BYTES)

__global__ void __launch_bounds__(256)
gemm_pipe(const __half* __restrict__ A16,
          int M,
          const __half* __restrict__ Bw,
          __half* __restrict__ C, int ldc)
{
    extern __shared__ char smem[];
    uint32_t sb0;
    asm("{ .reg .u64 t; cvta.to.shared.u64 t, %1; cvt.u32.u64 %0, t; }"
        : "=r"(sb0) : "l"(smem));

    const int tid  = threadIdx.x;
    const int wid  = tid >> 5;
    const int lane = tid & 31;
    const int wm   = wid >> 1;      // 0..3
    const int wn   = wid & 1;       // 0..1
    const int bm   = blockIdx.x * 128;
    const int bn   = blockIdx.y * 128;

    float acc[2][8][4];
#pragma unroll
    for (int i = 0; i < 2; i++)
#pragma unroll
        for (int j = 0; j < 8; j++)
#pragma unroll
            for (int q = 0; q < 4; q++) acc[i][j][q] = 0.f;

    const int q8 = lane >> 3;
    const int lg = lane & 7;

    // stage loader: 2 x 512 16B-chunks, 4 per thread
    auto load_stage = [&](int stage, int k0) {
        uint32_t sb = sb0 + stage * STG_BYTES;
#pragma unroll
        for (int i = 0; i < 4; i++) {
            int op  = i >> 1;
            int idx = (i & 1) * 256 + tid;
            int row = idx >> 2;
            int seg = (idx & 3) * 8;
            const __half* g;
            int grow;
            int sz = 16;
            if (op == 0) { g = A16; grow = bm + row; if (grow >= M) { grow = 0; sz = 0; } }
            else         { g = Bw;  grow = bn + row; }
            cp16(sb + op * OP_BYTES + row * 80 + seg * 2,
                 g + (size_t)grow * 256 + k0 + seg, sz);
        }
        CP_COMMIT();
    };

    load_stage(0, 0);

    for (int kb = 0; kb < 8; kb++) {
        if (kb < 7) load_stage((kb + 1) & 1, (kb + 1) * 32);
        if (kb < 7) CP_WAIT1(); else CP_WAIT0();
        __syncthreads();

        const uint32_t sb = sb0 + (kb & 1) * STG_BYTES;
        const uint32_t sA_b = sb;
        const uint32_t sBw_b = sb + OP_BYTES;

#pragma unroll
        for (int ks = 0; ks < 2; ks++) {
            uint32_t bw[16];
#pragma unroll
            for (int np = 0; np < 4; np++) {
                int nrow = wn * 64 + np * 16 + lg + ((q8 >> 1) ? 8 : 0);
                int bcol = ks * 32 + ((q8 & 1) ? 16 : 0);
                ldsm4(&bw[np * 4], sBw_b + nrow * 80 + bcol);
            }
#pragma unroll
            for (int mt = 0; mt < 2; mt++) {
                int arow = wm * 32 + mt * 16 + lg + ((q8 & 1) ? 8 : 0);
                int acol = ks * 32 + ((q8 >> 1) ? 16 : 0);
                uint32_t ah[4];
                ldsm4(ah, sA_b + arow * 80 + acol);
#pragma unroll
                for (int nt = 0; nt < 8; nt++) mma_f16(acc[mt][nt], ah, &bw[nt * 2]);
            }
        }
        __syncthreads();
    }

    // ---- epilogue (fp16) ----
#pragma unroll
    for (int mt = 0; mt < 2; mt++) {
#pragma unroll
        for (int nt = 0; nt < 8; nt++) {
            int gr0  = bm + wm * 32 + mt * 16 + (lane >> 2);
            int gcol = bn + wn * 64 + nt * 8 + (lane & 3) * 2;
#pragma unroll
            for (int h = 0; h < 2; h++) {
                int gr = gr0 + h * 8;
                if (gr < M) {
                    *(__half2*)(C + (size_t)gr * ldc + gcol) =
                        __floats2half2_rn(acc[mt][nt][h * 2 + 0], acc[mt][nt][h * 2 + 1]);
                }
            }
        }
    }
}

// ---------------------------------------------------------------------------
// Prep kernels
// ---------------------------------------------------------------------------
__global__ void convw_kernel(const float* __restrict__ W,
                             __half* __restrict__ w, int N, int total)
{
    int idx = blockIdx.x * blockDim.x + threadIdx.x;
    if (idx >= total) return;
    int n = idx % N;
    int k = (idx / N) & 255;
    int r = idx / (N * 256);
    w[((size_t)r * N + n) * 256 + k] = __float2half_rn(W[idx]);
}

__global__ void convx_kernel(const float* __restrict__ X,
                             __half* __restrict__ x16, size_t total)
{
    size_t i = (size_t)blockIdx.x * blockDim.x + threadIdx.x;
    if (i >= total) return;
    x16[i] = __float2half_rn(X[i]);
}

// ---------------------------------------------------------------------------
// CSR construction
// ---------------------------------------------------------------------------
__global__ void zero_int_kernel(int* p, int n)
{
    int i = blockIdx.x * blockDim.x + threadIdx.x;
    if (i < n) p[i] = 0;
}

__global__ void count_kernel(const int* __restrict__ ei,
                             const int* __restrict__ et,
                             int* __restrict__ cnt, int E)
{
    int e = blockIdx.x * blockDim.x + threadIdx.x;
    if (e < E) atomicAdd(&cnt[ei[E + e] * RELS + et[e]], 1);
}

__global__ void deg_kernel(const int* __restrict__ cnt, int* __restrict__ deg, int n)
{
    int i = blockIdx.x * blockDim.x + threadIdx.x;
    if (i < n) {
        int s = 0;
#pragma unroll
        for (int r = 0; r < RELS; r++) s += cnt[i * RELS + r];
        deg[i] = s;
    }
}

__global__ void scan_kernel(const int* __restrict__ deg, int* __restrict__ offs, int n)
{
    __shared__ int buf[1024];
    __shared__ int carry;
    const int tid = threadIdx.x;
    if (tid == 0) carry = 0;
    __syncthreads();
    for (int base = 0; base < n; base += 1024) {
        int i = base + tid;
        int v = (i < n) ? deg[i] : 0;
        buf[tid] = v;
        __syncthreads();
        for (int d = 1; d < 1024; d <<= 1) {
            int t = (tid >= d) ? buf[tid - d] : 0;
            __syncthreads();
            buf[tid] += t;
            __syncthreads();
        }
        if (i < n) offs[i] = carry + buf[tid] - v;
        __syncthreads();
        if (tid == 0) carry += buf[1023];
        __syncthreads();
    }
    if (tid == 0) offs[n] = carry;
}

__global__ void fill_kernel(const int* __restrict__ ei,
                            const int* __restrict__ et,
                            const int* __restrict__ offs,
                            int* __restrict__ cur,
                            unsigned* __restrict__ csr, int E)
{
    int e = blockIdx.x * blockDim.x + threadIdx.x;
    if (e < E) {
        int d = ei[E + e];
        int pos = offs[d] + atomicAdd(&cur[d], 1);
        csr[pos] = (unsigned)ei[e] | ((unsigned)et[e] << 16);
    }
}

// ---------------------------------------------------------------------------
// Gather. Layer 1: root(from Y1ext)+bias+messages, relu, fp16 round.
// ---------------------------------------------------------------------------
__global__ void __launch_bounds__(128)
gather1_kernel(const __half* __restrict__ Y,
               const unsigned* __restrict__ csr,
               const int* __restrict__ offs,
               const int* __restrict__ cnt,
               const float* __restrict__ bias,
               __half* __restrict__ h16)
{
    const int dst = blockIdx.x;
    const int tid = threadIdx.x;
    __shared__ float nrm[8];
    if (tid < 8) nrm[tid] = 1.0f / (float)max(cnt[dst * RELS + tid], 1);
    const int s = offs[dst], t = offs[dst + 1];
    __syncthreads();

    float2 bb = *(const float2*)(bias + tid * 2);
    float2 rt = __half22float2(__ldg((const __half2*)(Y + (size_t)dst * 2304 + 2048) + tid));
    float2 acc = make_float2(rt.x + bb.x, rt.y + bb.y);

    int e = s;
    for (; e + 4 <= t; e += 4) {
        unsigned p0 = csr[e], p1 = csr[e + 1], p2 = csr[e + 2], p3 = csr[e + 3];
        __half2 y0 = __ldg((const __half2*)(Y + (size_t)(p0 & 0xFFFFu) * 2304 + (p0 >> 16) * 256) + tid);
        __half2 y1 = __ldg((const __half2*)(Y + (size_t)(p1 & 0xFFFFu) * 2304 + (p1 >> 16) * 256) + tid);
        __half2 y2 = __ldg((const __half2*)(Y + (size_t)(p2 & 0xFFFFu) * 2304 + (p2 >> 16) * 256) + tid);
        __half2 y3 = __ldg((const __half2*)(Y + (size_t)(p3 & 0xFFFFu) * 2304 + (p3 >> 16) * 256) + tid);
        float2 f0 = __half22float2(y0), f1 = __half22float2(y1);
        float2 f2 = __half22float2(y2), f3 = __half22float2(y3);
        float n0 = nrm[p0 >> 16], n1 = nrm[p1 >> 16], n2 = nrm[p2 >> 16], n3 = nrm[p3 >> 16];
        acc.x += f0.x * n0 + f1.x * n1 + f2.x * n2 + f3.x * n3;
        acc.y += f0.y * n0 + f1.y * n1 + f2.y * n2 + f3.y * n3;
    }
    for (; e < t; e++) {
        unsigned p = csr[e];
        __half2 y = __ldg((const __half2*)(Y + (size_t)(p & 0xFFFFu) * 2304 + (p >> 16) * 256) + tid);
        float2 f = __half22float2(y);
        float n = nrm[p >> 16];
        acc.x += f.x * n;
        acc.y += f.y * n;
    }

    acc.x = fmaxf(acc.x, 0.f);
    acc.y = fmaxf(acc.y, 0.f);
    *(__half2*)(h16 + (size_t)dst * 256 + tid * 2) = __floats2half2_rn(acc.x, acc.y);
}

// Layer 2: out = root(from Y2ext) + bias + messages. 64 thr.
__global__ void __launch_bounds__(64)
gather2_kernel(const __half* __restrict__ Y,
               const unsigned* __restrict__ csr,
               const int* __restrict__ offs,
               const int* __restrict__ cnt,
               const float* __restrict__ bias,
               float* __restrict__ out)
{
    const int dst = blockIdx.x;
    const int tid = threadIdx.x;
    __shared__ float nrm[8];
    if (tid < 8) nrm[tid] = 1.0f / (float)max(cnt[dst * RELS + tid], 1);
    const int s = offs[dst], t = offs[dst + 1];
    __syncthreads();

    float2 bb = *(const float2*)(bias + tid * 2);
    float2 rt = __half22float2(__ldg((const __half2*)(Y + (size_t)dst * 1152 + 1024) + tid));
    float2 acc = make_float2(rt.x + bb.x, rt.y + bb.y);

    int e = s;
    for (; e + 4 <= t; e += 4) {
        unsigned p0 = csr[e], p1 = csr[e + 1], p2 = csr[e + 2], p3 = csr[e + 3];
        __half2 y0 = __ldg((const __half2*)(Y + (size_t)(p0 & 0xFFFFu) * 1152 + (p0 >> 16) * 128) + tid);
        __half2 y1 = __ldg((const __half2*)(Y + (size_t)(p1 & 0xFFFFu) * 1152 + (p1 >> 16) * 128) + tid);
        __half2 y2 = __ldg((const __half2*)(Y + (size_t)(p2 & 0xFFFFu) * 1152 + (p2 >> 16) * 128) + tid);
        __half2 y3 = __ldg((const __half2*)(Y + (size_t)(p3 & 0xFFFFu) * 1152 + (p3 >> 16) * 128) + tid);
        float2 f0 = __half22float2(y0), f1 = __half22float2(y1);
        float2 f2 = __half22float2(y2), f3 = __half22float2(y3);
        float n0 = nrm[p0 >> 16], n1 = nrm[p1 >> 16], n2 = nrm[p2 >> 16], n3 = nrm[p3 >> 16];
        acc.x += f0.x * n0 + f1.x * n1 + f2.x * n2 + f3.x * n3;
        acc.y += f0.y * n0 + f1.y * n1 + f2.y * n2 + f3.y * n3;
    }
    for (; e < t; e++) {
        unsigned p = csr[e];
        __half2 y = __ldg((const __half2*)(Y + (size_t)(p & 0xFFFFu) * 1152 + (p >> 16) * 128) + tid);
        float2 f = __half22float2(y);
        float n = nrm[p >> 16];
        acc.x += f.x * n;
        acc.y += f.y * n;
    }
    *(float2*)(out + (size_t)dst * 128 + tid * 2) = acc;
}

// ---------------------------------------------------------------------------
extern "C" void kernel_launch(void* const* d_in, const int* in_sizes, int n_in,
                              void* d_out, int out_size)
{
    const float* x     = (const float*)d_in[0];
    const int*   ei    = (const int*)d_in[1];
    const int*   et    = (const int*)d_in[2];
    const float* W1    = (const float*)d_in[3];
    const float* root1 = (const float*)d_in[4];
    const float* b1    = (const float*)d_in[5];
    const float* W2    = (const float*)d_in[6];
    const float* root2 = (const float*)d_in[7];
    const float* b2    = (const float*)d_in[8];
    float*       out   = (float*)d_out;

    const int N = in_sizes[0] / 256;
    const int E = in_sizes[2];

    __half *Y1, *Y2, *x16, *h16, *w1, *w2;
    int *cnt, *deg, *offs, *cur;
    unsigned* csr;
    cudaGetSymbolAddress((void**)&Y1, g_Y1);
    cudaGetSymbolAddress((void**)&Y2, g_Y2);
    cudaGetSymbolAddress((void**)&cnt, g_cnt);
    cudaGetSymbolAddress((void**)&deg, g_deg);
    cudaGetSymbolAddress((void**)&offs, g_offs);
    cudaGetSymbolAddress((void**)&cur, g_cur);
    cudaGetSymbolAddress((void**)&csr, g_csr);
    cudaGetSymbolAddress((void**)&x16, g_x16);
    cudaGetSymbolAddress((void**)&h16, g_h16);
    cudaGetSymbolAddress((void**)&w1, g_w1);
    cudaGetSymbolAddress((void**)&w2, g_w2);

    static cudaStream_t sCsr = nullptr;
    static cudaEvent_t evFork = nullptr, evCsrDone = nullptr;
    static int attr_set = 0;
    if (!attr_set) {
        cudaFuncSetAttribute(gemm_pipe, cudaFuncAttributeMaxDynamicSharedMemorySize, SMEMP);
        cudaStreamCreateWithFlags(&sCsr, cudaStreamNonBlocking);
        cudaEventCreateWithFlags(&evFork, cudaEventDisableTiming);
        cudaEventCreateWithFlags(&evCsrDone, cudaEventDisableTiming);
        attr_set = 1;
    }

    // ---- fork: CSR build + layer-2 weight prep on side stream ----
    cudaEventRecord(evFork, 0);
    cudaStreamWaitEvent(sCsr, evFork, 0);

    zero_int_kernel<<<(N * RELS + 255) / 256, 256, 0, sCsr>>>(cnt, N * RELS);
    zero_int_kernel<<<(N + 255) / 256, 256, 0, sCsr>>>(cur, N);
    count_kernel<<<(E + 255) / 256, 256, 0, sCsr>>>(ei, et, cnt, E);
    deg_kernel<<<(N + 255) / 256, 256, 0, sCsr>>>(cnt, deg, N);
    scan_kernel<<<1, 1024, 0, sCsr>>>(deg, offs, N);
    fill_kernel<<<(E + 255) / 256, 256, 0, sCsr>>>(ei, et, offs, cur, csr, E);
    convw_kernel<<<(8 * 256 * 128 + 255) / 256, 256, 0, sCsr>>>(W2, w2, 128, 8 * 256 * 128);
    convw_kernel<<<(256 * 128 + 255) / 256, 256, 0, sCsr>>>(root2, w2 + 1024 * 256, 128, 256 * 128);
    cudaEventRecord(evCsrDone, sCsr);

    // main stream: layer-1 weight + input prep
    convw_kernel<<<(8 * 256 * 256 + 255) / 256, 256>>>(W1, w1, 256, 8 * 256 * 256);
    convw_kernel<<<(256 * 256 + 255) / 256, 256>>>(root1, w1 + 2048 * 256, 256, 256 * 256);
    convx_kernel<<<(int)(((size_t)N * 256 + 255) / 256), 256>>>(x, x16, (size_t)N * 256);

    const int mtiles = (N + 127) / 128;

    // ---- layer 1: 18 n-tiles (8 rel x 2 + root x 2) ----
    gemm_pipe<<<dim3(mtiles, 18), 256, SMEMP>>>(x16, N, w1, Y1, 2304);

    // join: gather1 needs the CSR (and GEMM2 the W2 prep, covered by same event)
    cudaStreamWaitEvent(0, evCsrDone, 0);
    gather1_kernel<<<N, 128>>>(Y1, csr, offs, cnt, b1, h16);

    // ---- layer 2: 9 n-tiles (8 rel + root) ----
    gemm_pipe<<<dim3(mtiles, 9), 256, SMEMP>>>(h16, N, w2, Y2, 1152);
    gather2_kernel<<<N, 64>>>(Y2, csr, offs, cnt, b2, out);
}